// round 1
// baseline (speedup 1.0000x reference)
#include <cuda_runtime.h>
#include <math.h>

#define BB 8
#define SS 1024
#define EE 1024
#define HH 16
#define DD 64
#define M_TOT (BB*SS)   /* 8192 */

// Scratch (zero-init .bss-style device globals; no allocations)
__device__ float g_Q[(size_t)M_TOT * EE];
__device__ float g_K[(size_t)M_TOT * EE];
__device__ float g_V[(size_t)M_TOT * EE];
__device__ float g_O[(size_t)M_TOT * EE];
__device__ float g_R[(size_t)M_TOT * EE];

// ---------------------------------------------------------------------------
// QKV GEMM: C[m,n] = sum_k X[m,k] * W[k,n], optional per-(batch,col) gate*2
// 128x128 tile, BK=16, 256 threads, 8x8 per thread.
// which: 0 -> g_Q, 1 -> g_K, 2 -> g_V
// ---------------------------------------------------------------------------
__global__ __launch_bounds__(256) void qkv_gemm_kernel(
    const float* __restrict__ Xin, const float* __restrict__ W,
    const float* __restrict__ gate, int which)
{
    __shared__ float As[16][132];
    __shared__ float Bs[16][128];

    float* Cout = (which == 0) ? g_Q : (which == 1) ? g_K : g_V;

    const int rowBase = blockIdx.y * 128;
    const int colBase = blockIdx.x * 128;
    const int tid = threadIdx.x;
    const int tm = tid >> 4;     // 0..15
    const int tn = tid & 15;     // 0..15

    float acc[8][8];
#pragma unroll
    for (int i = 0; i < 8; i++)
#pragma unroll
        for (int j = 0; j < 8; j++) acc[i][j] = 0.f;

    for (int kt = 0; kt < EE; kt += 16) {
        // A tile -> transposed smem As[k][m]
#pragma unroll
        for (int i = 0; i < 2; i++) {
            int idx = tid + i * 256;          // 0..511
            int r = idx >> 2;                 // 0..127
            int k4 = (idx & 3) * 4;           // 0,4,8,12
            float4 v = *(const float4*)(Xin + (size_t)(rowBase + r) * EE + kt + k4);
            As[k4 + 0][r] = v.x;
            As[k4 + 1][r] = v.y;
            As[k4 + 2][r] = v.z;
            As[k4 + 3][r] = v.w;
        }
        // B tile natural Bs[k][n]
#pragma unroll
        for (int i = 0; i < 2; i++) {
            int idx = tid + i * 256;
            int r = idx >> 5;                 // 0..15
            int c4 = (idx & 31) * 4;          // 0..124
            *(float4*)(&Bs[r][c4]) =
                *(const float4*)(W + (size_t)(kt + r) * EE + colBase + c4);
        }
        __syncthreads();
#pragma unroll
        for (int k = 0; k < 16; k++) {
            float a[8], b[8];
            *(float4*)(a)     = *(const float4*)(&As[k][tm * 8]);
            *(float4*)(a + 4) = *(const float4*)(&As[k][tm * 8 + 4]);
            *(float4*)(b)     = *(const float4*)(&Bs[k][tn * 8]);
            *(float4*)(b + 4) = *(const float4*)(&Bs[k][tn * 8 + 4]);
#pragma unroll
            for (int i = 0; i < 8; i++)
#pragma unroll
                for (int j = 0; j < 8; j++)
                    acc[i][j] = fmaf(a[i], b[j], acc[i][j]);
        }
        __syncthreads();
    }

    const int batch = rowBase / SS;  // 128 | 1024 -> whole block in one batch
    float gv[8];
    if (gate) {
#pragma unroll
        for (int j = 0; j < 8; j++)
            gv[j] = gate[(size_t)batch * EE + colBase + tn * 8 + j] * 2.0f;
    } else {
#pragma unroll
        for (int j = 0; j < 8; j++) gv[j] = 1.0f;
    }
#pragma unroll
    for (int i = 0; i < 8; i++) {
        size_t row = rowBase + tm * 8 + i;
        float4 o0, o1;
        o0.x = acc[i][0] * gv[0]; o0.y = acc[i][1] * gv[1];
        o0.z = acc[i][2] * gv[2]; o0.w = acc[i][3] * gv[3];
        o1.x = acc[i][4] * gv[4]; o1.y = acc[i][5] * gv[5];
        o1.z = acc[i][6] * gv[6]; o1.w = acc[i][7] * gv[7];
        *(float4*)(Cout + row * EE + colBase + tn * 8)     = o0;
        *(float4*)(Cout + row * EE + colBase + tn * 8 + 4) = o1;
    }
}

// ---------------------------------------------------------------------------
// Output projection (NT): R[m,n] = sum_k O[m,k] * Wo[n,k] + X[m,n]
// ---------------------------------------------------------------------------
__global__ __launch_bounds__(256) void out_gemm_kernel(
    const float* __restrict__ Wo, const float* __restrict__ Xin)
{
    __shared__ float As[16][132];
    __shared__ float Bs[16][132];

    const int rowBase = blockIdx.y * 128;
    const int colBase = blockIdx.x * 128;
    const int tid = threadIdx.x;
    const int tm = tid >> 4;
    const int tn = tid & 15;

    float acc[8][8];
#pragma unroll
    for (int i = 0; i < 8; i++)
#pragma unroll
        for (int j = 0; j < 8; j++) acc[i][j] = 0.f;

    for (int kt = 0; kt < EE; kt += 16) {
#pragma unroll
        for (int i = 0; i < 2; i++) {
            int idx = tid + i * 256;
            int r = idx >> 2;
            int k4 = (idx & 3) * 4;
            float4 v = *(const float4*)(g_O + (size_t)(rowBase + r) * EE + kt + k4);
            As[k4 + 0][r] = v.x;
            As[k4 + 1][r] = v.y;
            As[k4 + 2][r] = v.z;
            As[k4 + 3][r] = v.w;
            // Wo is [n,k] row-major: same transposed-load pattern, r = n-offset
            float4 w = *(const float4*)(Wo + (size_t)(colBase + r) * EE + kt + k4);
            Bs[k4 + 0][r] = w.x;
            Bs[k4 + 1][r] = w.y;
            Bs[k4 + 2][r] = w.z;
            Bs[k4 + 3][r] = w.w;
        }
        __syncthreads();
#pragma unroll
        for (int k = 0; k < 16; k++) {
            float a[8], b[8];
            *(float4*)(a)     = *(const float4*)(&As[k][tm * 8]);
            *(float4*)(a + 4) = *(const float4*)(&As[k][tm * 8 + 4]);
            *(float4*)(b)     = *(const float4*)(&Bs[k][tn * 8]);
            *(float4*)(b + 4) = *(const float4*)(&Bs[k][tn * 8 + 4]);
#pragma unroll
            for (int i = 0; i < 8; i++)
#pragma unroll
                for (int j = 0; j < 8; j++)
                    acc[i][j] = fmaf(a[i], b[j], acc[i][j]);
        }
        __syncthreads();
    }

#pragma unroll
    for (int i = 0; i < 8; i++) {
        size_t row = rowBase + tm * 8 + i;
        float4 x0 = *(const float4*)(Xin + row * EE + colBase + tn * 8);
        float4 x1 = *(const float4*)(Xin + row * EE + colBase + tn * 8 + 4);
        float4 o0, o1;
        o0.x = acc[i][0] + x0.x; o0.y = acc[i][1] + x0.y;
        o0.z = acc[i][2] + x0.z; o0.w = acc[i][3] + x0.w;
        o1.x = acc[i][4] + x1.x; o1.y = acc[i][5] + x1.y;
        o1.z = acc[i][6] + x1.z; o1.w = acc[i][7] + x1.w;
        *(float4*)(g_R + row * EE + colBase + tn * 8)     = o0;
        *(float4*)(g_R + row * EE + colBase + tn * 8 + 4) = o1;
    }
}

// ---------------------------------------------------------------------------
// Flash attention: per (b, h, 64-query tile). 64-key tiles, online softmax.
// 256 threads as 16x16; each thread owns 4 q-rows x 4 cols.
// Dynamic smem: Qs/Ks (transposed [d][·]), Vs [k][d], Ps [k][q]; pad 68.
// ---------------------------------------------------------------------------
#define ATTN_PAD 68
#define ATTN_SMEM (4 * 64 * ATTN_PAD * 4)

__global__ __launch_bounds__(256) void attn_kernel()
{
    extern __shared__ float sm[];
    float (*Qs)[ATTN_PAD] = (float(*)[ATTN_PAD])(sm);
    float (*Ks)[ATTN_PAD] = (float(*)[ATTN_PAD])(sm + 64 * ATTN_PAD);
    float (*Vs)[ATTN_PAD] = (float(*)[ATTN_PAD])(sm + 2 * 64 * ATTN_PAD);
    float (*Ps)[ATTN_PAD] = (float(*)[ATTN_PAD])(sm + 3 * 64 * ATTN_PAD);

    const int qt = blockIdx.x;   // 0..15
    const int h  = blockIdx.y;   // 0..15
    const int b  = blockIdx.z;   // 0..7
    const int tid = threadIdx.x;
    const int ty = tid >> 4;     // 0..15 (q group)
    const int tx = tid & 15;     // 0..15 (k / d group)

    const size_t base = ((size_t)b * SS) * EE + (size_t)h * DD;

    // Load Q transposed: Qs[d][q]
#pragma unroll
    for (int i = 0; i < 4; i++) {
        int idx = tid + i * 256;          // 0..1023
        int q = idx >> 4;                 // 0..63
        int d4 = (idx & 15) * 4;
        float4 v = *(const float4*)(g_Q + base + (size_t)(qt * 64 + q) * EE + d4);
        Qs[d4 + 0][q] = v.x; Qs[d4 + 1][q] = v.y;
        Qs[d4 + 2][q] = v.z; Qs[d4 + 3][q] = v.w;
    }

    float m[4], l[4], acc[4][4];
#pragma unroll
    for (int i = 0; i < 4; i++) {
        m[i] = -1e30f; l[i] = 0.f;
#pragma unroll
        for (int j = 0; j < 4; j++) acc[i][j] = 0.f;
    }

    const float sc = 0.125f;  // 1/sqrt(64)

    for (int kt = 0; kt < SS / 64; kt++) {
        __syncthreads();  // protect Ks/Vs reuse (and Qs visibility on iter 0)
#pragma unroll
        for (int i = 0; i < 4; i++) {
            int idx = tid + i * 256;
            int r = idx >> 4;             // key row 0..63
            int d4 = (idx & 15) * 4;
            float4 kv = *(const float4*)(g_K + base + (size_t)(kt * 64 + r) * EE + d4);
            Ks[d4 + 0][r] = kv.x; Ks[d4 + 1][r] = kv.y;
            Ks[d4 + 2][r] = kv.z; Ks[d4 + 3][r] = kv.w;
            float4 vv = *(const float4*)(g_V + base + (size_t)(kt * 64 + r) * EE + d4);
            *(float4*)(&Vs[r][d4]) = vv;
        }
        __syncthreads();

        // Scores: s[i][j] = sum_d Q[q][d] * K[k][d]
        float s[4][4];
#pragma unroll
        for (int i = 0; i < 4; i++)
#pragma unroll
            for (int j = 0; j < 4; j++) s[i][j] = 0.f;
#pragma unroll
        for (int d = 0; d < 64; d++) {
            float4 a = *(const float4*)(&Qs[d][ty * 4]);
            float4 bb = *(const float4*)(&Ks[d][tx * 4]);
            float av[4] = {a.x, a.y, a.z, a.w};
            float bv[4] = {bb.x, bb.y, bb.z, bb.w};
#pragma unroll
            for (int i = 0; i < 4; i++)
#pragma unroll
                for (int j = 0; j < 4; j++)
                    s[i][j] = fmaf(av[i], bv[j], s[i][j]);
        }

        // Online softmax per q-row (replicated across the 16 tx lanes)
#pragma unroll
        for (int i = 0; i < 4; i++) {
            float mx = fmaxf(fmaxf(s[i][0], s[i][1]), fmaxf(s[i][2], s[i][3]));
            mx *= sc;
#pragma unroll
            for (int off = 1; off < 16; off <<= 1)
                mx = fmaxf(mx, __shfl_xor_sync(0xffffffffu, mx, off));
            float mnew = fmaxf(m[i], mx);
            float corr = __expf(m[i] - mnew);
            float ps = 0.f;
#pragma unroll
            for (int j = 0; j < 4; j++) {
                float p = __expf(fmaf(s[i][j], sc, -mnew));
                Ps[tx * 4 + j][ty * 4 + i] = p;   // store transposed [k][q]
                ps += p;
            }
#pragma unroll
            for (int off = 1; off < 16; off <<= 1)
                ps += __shfl_xor_sync(0xffffffffu, ps, off);
            l[i] = l[i] * corr + ps;
            m[i] = mnew;
#pragma unroll
            for (int j = 0; j < 4; j++) acc[i][j] *= corr;
        }
        __syncthreads();

        // PV: acc[i][j] += sum_k P[q][k] * V[k][d]
#pragma unroll
        for (int k = 0; k < 64; k++) {
            float4 a = *(const float4*)(&Ps[k][ty * 4]);
            float4 bb = *(const float4*)(&Vs[k][tx * 4]);
            float av[4] = {a.x, a.y, a.z, a.w};
            float bv[4] = {bb.x, bb.y, bb.z, bb.w};
#pragma unroll
            for (int i = 0; i < 4; i++)
#pragma unroll
                for (int j = 0; j < 4; j++)
                    acc[i][j] = fmaf(av[i], bv[j], acc[i][j]);
        }
    }

    // Epilogue: divide by l, write O[b, q, h*D + d]
#pragma unroll
    for (int i = 0; i < 4; i++) {
        float inv = 1.f / l[i];
        size_t row = (size_t)(qt * 64 + ty * 4 + i);
        float4 o;
        o.x = acc[i][0] * inv; o.y = acc[i][1] * inv;
        o.z = acc[i][2] * inv; o.w = acc[i][3] * inv;
        *(float4*)(g_O + base + row * EE + tx * 4) = o;
    }
}

// ---------------------------------------------------------------------------
// LayerNorm: one block per row of 1024, 256 threads x float4
// ---------------------------------------------------------------------------
__global__ __launch_bounds__(256) void ln_kernel(
    const float* __restrict__ gamma, const float* __restrict__ beta,
    float* __restrict__ out)
{
    const int row = blockIdx.x;
    const int tid = threadIdx.x;
    const float4 v = *(const float4*)(g_R + (size_t)row * EE + tid * 4);

    float s1 = v.x + v.y + v.z + v.w;
    float s2 = v.x * v.x + v.y * v.y + v.z * v.z + v.w * v.w;

    __shared__ float sh1[8], sh2[8];
#pragma unroll
    for (int off = 16; off > 0; off >>= 1) {
        s1 += __shfl_xor_sync(0xffffffffu, s1, off);
        s2 += __shfl_xor_sync(0xffffffffu, s2, off);
    }
    const int warp = tid >> 5;
    if ((tid & 31) == 0) { sh1[warp] = s1; sh2[warp] = s2; }
    __syncthreads();
    float t1 = 0.f, t2 = 0.f;
#pragma unroll
    for (int w = 0; w < 8; w++) { t1 += sh1[w]; t2 += sh2[w]; }

    const float mean = t1 * (1.0f / EE);
    const float var  = t2 * (1.0f / EE) - mean * mean;
    const float inv  = rsqrtf(var + 1e-6f);

    const float4 g  = *(const float4*)(gamma + tid * 4);
    const float4 bt = *(const float4*)(beta + tid * 4);
    float4 o;
    o.x = (v.x - mean) * inv * g.x + bt.x;
    o.y = (v.y - mean) * inv * g.y + bt.y;
    o.z = (v.z - mean) * inv * g.z + bt.z;
    o.w = (v.w - mean) * inv * g.w + bt.w;
    *(float4*)(out + (size_t)row * EE + tid * 4) = o;
}

// ---------------------------------------------------------------------------
extern "C" void kernel_launch(void* const* d_in, const int* in_sizes, int n_in,
                              void* d_out, int out_size)
{
    const float* X     = (const float*)d_in[0];
    const float* gQ    = (const float*)d_in[1];
    const float* gK    = (const float*)d_in[2];
    const float* Wq    = (const float*)d_in[3];
    const float* Wk    = (const float*)d_in[4];
    const float* Wv    = (const float*)d_in[5];
    const float* Wo    = (const float*)d_in[6];
    const float* gamma = (const float*)d_in[7];
    const float* beta  = (const float*)d_in[8];
    float* out = (float*)d_out;

    dim3 gemm_grid(EE / 128, M_TOT / 128);   // (8, 64)

    qkv_gemm_kernel<<<gemm_grid, 256>>>(X, Wq, gQ, 0);
    qkv_gemm_kernel<<<gemm_grid, 256>>>(X, Wk, gK, 1);
    qkv_gemm_kernel<<<gemm_grid, 256>>>(X, Wv, nullptr, 2);

    cudaFuncSetAttribute(attn_kernel,
                         cudaFuncAttributeMaxDynamicSharedMemorySize, ATTN_SMEM);
    attn_kernel<<<dim3(SS / 64, HH, BB), 256, ATTN_SMEM>>>();

    out_gemm_kernel<<<gemm_grid, 256>>>(Wo, X);
    ln_kernel<<<M_TOT, 256>>>(gamma, beta, out);
}

// round 3
// speedup vs baseline: 1.2359x; 1.2359x over previous
#include <cuda_runtime.h>
#include <cuda_bf16.h>
#include <math.h>
#include <stdint.h>

#define BB 8
#define SS 1024
#define EE 1024
#define HH 16
#define DD 64
#define M_TOT (BB*SS)   /* 8192 */

// Scratch (no allocations allowed)
__device__ float g_Q[(size_t)M_TOT * EE];
__device__ float g_K[(size_t)M_TOT * EE];
__device__ float g_V[(size_t)M_TOT * EE];
__device__ float g_O[(size_t)M_TOT * EE];
__device__ float g_R[(size_t)M_TOT * EE];

// ---------------------------------------------------------------------------
// bf16 split-GEMM via mma.sync (family-target safe; no tcgen05)
// C[128x128 tile] = A[M,K] @ B, K=1024, BK=32, double-buffered smem.
// mode 0: g_Q = X@Wq, gate*2   (B = Wq [K,N], transpose on store)
// mode 1: g_K = X@Wk, gate*2
// mode 2: g_V = X@Wv
// mode 3: g_R = g_O@Wo^T + X   (B = Wo [N,K], already K-major)
// Precision: x = hi(bf16) + lo(bf16); D += Ah*Bh + Ah*Bl + Al*Bh  (~2^-18)
// ---------------------------------------------------------------------------
#define BK 32
#define ROW_BF 36                 /* bf16 per smem row (32 + pad 4) */
#define ROW_U32 18
#define TILE_BYTES (128 * ROW_BF * 2)           /* 9216 */
#define STAGE_BYTES (4 * TILE_BYTES)            /* Ah, Al, Bh, Bl = 36864 */
#define GEMM_SMEM (2 * STAGE_BYTES)             /* 73728 */

__device__ __forceinline__ void mma_bf16(float* c, const uint32_t* a,
                                         uint32_t b0, uint32_t b1) {
    asm volatile(
        "mma.sync.aligned.m16n8k16.row.col.f32.bf16.bf16.f32 "
        "{%0,%1,%2,%3}, {%4,%5,%6,%7}, {%8,%9}, {%0,%1,%2,%3};"
        : "+f"(c[0]), "+f"(c[1]), "+f"(c[2]), "+f"(c[3])
        : "r"(a[0]), "r"(a[1]), "r"(a[2]), "r"(a[3]), "r"(b0), "r"(b1));
}

__global__ __launch_bounds__(256, 1) void gemm_bf16x2_kernel(
    const float* __restrict__ Ain, const float* __restrict__ Bin,
    const float* __restrict__ Aux, int mode)
{
    extern __shared__ char smb[];

    const float* A = (mode == 3) ? g_O : Ain;
    float* C = (mode == 0) ? g_Q : (mode == 1) ? g_K : (mode == 2) ? g_V : g_R;

    const int tid = threadIdx.x;
    const int wid = tid >> 5;
    const int lane = tid & 31;
    const int g = lane >> 2;       // 0..7
    const int tig = lane & 3;      // 0..3
    const int wm = wid >> 1;       // 0..3  (M warp)
    const int wn = wid & 1;        // 0..1  (N warp)
    const int colBase = blockIdx.x * 128;
    const int rowBase = blockIdx.y * 128;

    float c[2][8][4];
#pragma unroll
    for (int mt = 0; mt < 2; mt++)
#pragma unroll
        for (int nt = 0; nt < 8; nt++)
#pragma unroll
            for (int r = 0; r < 4; r++) c[mt][nt][r] = 0.f;

    const float* Abase = A + (size_t)rowBase * EE;

    float4 ra[4], rb[4];

    // ---- producer helpers (inlined via lambdas) ----
    auto ldgA = [&](int kt) {
        const float* Ap = Abase + kt * BK;
#pragma unroll
        for (int i = 0; i < 4; i++) {
            int idx = tid + i * 256;
            int r = idx >> 3;
            int c4 = (idx & 7) * 4;
            ra[i] = *(const float4*)(Ap + (size_t)r * EE + c4);
        }
    };
    auto ldgB = [&](int kt) {
        if (mode != 3) {
            const float* Bp = Bin + (size_t)(kt * BK) * EE + colBase;
#pragma unroll
            for (int i = 0; i < 4; i++) {
                int idx = tid + i * 256;
                int k = idx >> 5;
                int n4 = (idx & 31) * 4;
                rb[i] = *(const float4*)(Bp + (size_t)k * EE + n4);
            }
        } else {
            const float* Bp = Bin + (size_t)colBase * EE + kt * BK;
#pragma unroll
            for (int i = 0; i < 4; i++) {
                int idx = tid + i * 256;
                int r = idx >> 3;
                int c4 = (idx & 7) * 4;
                rb[i] = *(const float4*)(Bp + (size_t)r * EE + c4);
            }
        }
    };
    auto stsTile = [&](int buf) {
        char* st = smb + buf * STAGE_BYTES;
        uint32_t* Ah = (uint32_t*)(st);
        uint32_t* Al = (uint32_t*)(st + TILE_BYTES);
        // A: rows r, k c4..c4+3
#pragma unroll
        for (int i = 0; i < 4; i++) {
            int idx = tid + i * 256;
            int r = idx >> 3;
            int c4 = (idx & 7) * 4;
            float x0 = ra[i].x, x1 = ra[i].y, x2 = ra[i].z, x3 = ra[i].w;
            __nv_bfloat162 h01 = __floats2bfloat162_rn(x0, x1);
            __nv_bfloat162 h23 = __floats2bfloat162_rn(x2, x3);
            __nv_bfloat162 l01 = __floats2bfloat162_rn(
                x0 - __bfloat162float(h01.x), x1 - __bfloat162float(h01.y));
            __nv_bfloat162 l23 = __floats2bfloat162_rn(
                x2 - __bfloat162float(h23.x), x3 - __bfloat162float(h23.y));
            int o = r * ROW_U32 + (c4 >> 1);
            Ah[o]     = *(uint32_t*)&h01;
            Ah[o + 1] = *(uint32_t*)&h23;
            Al[o]     = *(uint32_t*)&l01;
            Al[o + 1] = *(uint32_t*)&l23;
        }
        __nv_bfloat16* Bh = (__nv_bfloat16*)(st + 2 * TILE_BYTES);
        __nv_bfloat16* Bl = (__nv_bfloat16*)(st + 3 * TILE_BYTES);
        if (mode != 3) {
            // transpose [k][n] -> [n][k]
#pragma unroll
            for (int i = 0; i < 4; i++) {
                int idx = tid + i * 256;
                int k = idx >> 5;
                int n4 = (idx & 31) * 4;
                float vv[4] = {rb[i].x, rb[i].y, rb[i].z, rb[i].w};
#pragma unroll
                for (int j = 0; j < 4; j++) {
                    __nv_bfloat16 h = __float2bfloat16(vv[j]);
                    float l = vv[j] - __bfloat162float(h);
                    Bh[(n4 + j) * ROW_BF + k] = h;
                    Bl[(n4 + j) * ROW_BF + k] = __float2bfloat16(l);
                }
            }
        } else {
            uint32_t* Bh32 = (uint32_t*)Bh;
            uint32_t* Bl32 = (uint32_t*)Bl;
#pragma unroll
            for (int i = 0; i < 4; i++) {
                int idx = tid + i * 256;
                int r = idx >> 3;
                int c4 = (idx & 7) * 4;
                float x0 = rb[i].x, x1 = rb[i].y, x2 = rb[i].z, x3 = rb[i].w;
                __nv_bfloat162 h01 = __floats2bfloat162_rn(x0, x1);
                __nv_bfloat162 h23 = __floats2bfloat162_rn(x2, x3);
                __nv_bfloat162 l01 = __floats2bfloat162_rn(
                    x0 - __bfloat162float(h01.x), x1 - __bfloat162float(h01.y));
                __nv_bfloat162 l23 = __floats2bfloat162_rn(
                    x2 - __bfloat162float(h23.x), x3 - __bfloat162float(h23.y));
                int o = r * ROW_U32 + (c4 >> 1);
                Bh32[o]     = *(uint32_t*)&h01;
                Bh32[o + 1] = *(uint32_t*)&h23;
                Bl32[o]     = *(uint32_t*)&l01;
                Bl32[o + 1] = *(uint32_t*)&l23;
            }
        }
    };

    // ---- prologue ----
    ldgA(0); ldgB(0);
    stsTile(0);
    __syncthreads();

    const int NT = EE / BK;  // 32
    for (int kt = 0; kt < NT; kt++) {
        const int buf = kt & 1;
        if (kt + 1 < NT) { ldgA(kt + 1); ldgB(kt + 1); }

        const char* st = smb + buf * STAGE_BYTES;
        const uint32_t* Ah = (const uint32_t*)(st);
        const uint32_t* Al = (const uint32_t*)(st + TILE_BYTES);
        const uint32_t* Bh = (const uint32_t*)(st + 2 * TILE_BYTES);
        const uint32_t* Bl = (const uint32_t*)(st + 3 * TILE_BYTES);

#pragma unroll
        for (int ks = 0; ks < 2; ks++) {   // two k16 steps in BK=32
            uint32_t ah[2][4], al[2][4];
#pragma unroll
            for (int mt = 0; mt < 2; mt++) {
                int r0 = (wm * 32 + mt * 16 + g) * ROW_U32 + ks * 8 + tig;
                int r1 = r0 + 8 * ROW_U32;
                ah[mt][0] = Ah[r0];     ah[mt][1] = Ah[r1];
                ah[mt][2] = Ah[r0 + 4]; ah[mt][3] = Ah[r1 + 4];
                al[mt][0] = Al[r0];     al[mt][1] = Al[r1];
                al[mt][2] = Al[r0 + 4]; al[mt][3] = Al[r1 + 4];
            }
#pragma unroll
            for (int nt = 0; nt < 8; nt++) {
                int n0 = (wn * 64 + nt * 8 + g) * ROW_U32 + ks * 8 + tig;
                uint32_t bh0 = Bh[n0], bh1 = Bh[n0 + 4];
                uint32_t bl0 = Bl[n0], bl1 = Bl[n0 + 4];
#pragma unroll
                for (int mt = 0; mt < 2; mt++) {
                    mma_bf16(c[mt][nt], ah[mt], bh0, bh1);
                    mma_bf16(c[mt][nt], ah[mt], bl0, bl1);
                    mma_bf16(c[mt][nt], al[mt], bh0, bh1);
                }
            }
        }
        __syncthreads();
        if (kt + 1 < NT) {
            stsTile((kt + 1) & 1);
        }
        __syncthreads();
    }

    // ---- epilogue: fused gate / residual, write fp32 ----
    const int batch = rowBase / SS;
#pragma unroll
    for (int mt = 0; mt < 2; mt++) {
        int row0 = rowBase + wm * 32 + mt * 16 + g;
#pragma unroll
        for (int nt = 0; nt < 8; nt++) {
            int col = colBase + wn * 64 + nt * 8 + 2 * tig;
            float v00 = c[mt][nt][0], v01 = c[mt][nt][1];
            float v10 = c[mt][nt][2], v11 = c[mt][nt][3];
            if (mode <= 1) {
                float2 gv = *(const float2*)(Aux + (size_t)batch * EE + col);
                v00 *= gv.x * 2.0f; v01 *= gv.y * 2.0f;
                v10 *= gv.x * 2.0f; v11 *= gv.y * 2.0f;
            } else if (mode == 3) {
                float2 x0 = *(const float2*)(Aux + (size_t)row0 * EE + col);
                float2 x1 = *(const float2*)(Aux + (size_t)(row0 + 8) * EE + col);
                v00 += x0.x; v01 += x0.y;
                v10 += x1.x; v11 += x1.y;
            }
            *(float2*)(C + (size_t)row0 * EE + col) = make_float2(v00, v01);
            *(float2*)(C + (size_t)(row0 + 8) * EE + col) = make_float2(v10, v11);
        }
    }
}

// ---------------------------------------------------------------------------
// Flash attention (fp32 SIMT, unchanged from R1)
// ---------------------------------------------------------------------------
#define ATTN_PAD 68
#define ATTN_SMEM (4 * 64 * ATTN_PAD * 4)

__global__ __launch_bounds__(256) void attn_kernel()
{
    extern __shared__ float sm[];
    float (*Qs)[ATTN_PAD] = (float(*)[ATTN_PAD])(sm);
    float (*Ks)[ATTN_PAD] = (float(*)[ATTN_PAD])(sm + 64 * ATTN_PAD);
    float (*Vs)[ATTN_PAD] = (float(*)[ATTN_PAD])(sm + 2 * 64 * ATTN_PAD);
    float (*Ps)[ATTN_PAD] = (float(*)[ATTN_PAD])(sm + 3 * 64 * ATTN_PAD);

    const int qt = blockIdx.x;
    const int h  = blockIdx.y;
    const int b  = blockIdx.z;
    const int tid = threadIdx.x;
    const int ty = tid >> 4;
    const int tx = tid & 15;

    const size_t base = ((size_t)b * SS) * EE + (size_t)h * DD;

#pragma unroll
    for (int i = 0; i < 4; i++) {
        int idx = tid + i * 256;
        int q = idx >> 4;
        int d4 = (idx & 15) * 4;
        float4 v = *(const float4*)(g_Q + base + (size_t)(qt * 64 + q) * EE + d4);
        Qs[d4 + 0][q] = v.x; Qs[d4 + 1][q] = v.y;
        Qs[d4 + 2][q] = v.z; Qs[d4 + 3][q] = v.w;
    }

    float m[4], l[4], acc[4][4];
#pragma unroll
    for (int i = 0; i < 4; i++) {
        m[i] = -1e30f; l[i] = 0.f;
#pragma unroll
        for (int j = 0; j < 4; j++) acc[i][j] = 0.f;
    }

    const float sc = 0.125f;

    for (int kt = 0; kt < SS / 64; kt++) {
        __syncthreads();
#pragma unroll
        for (int i = 0; i < 4; i++) {
            int idx = tid + i * 256;
            int r = idx >> 4;
            int d4 = (idx & 15) * 4;
            float4 kv = *(const float4*)(g_K + base + (size_t)(kt * 64 + r) * EE + d4);
            Ks[d4 + 0][r] = kv.x; Ks[d4 + 1][r] = kv.y;
            Ks[d4 + 2][r] = kv.z; Ks[d4 + 3][r] = kv.w;
            float4 vv = *(const float4*)(g_V + base + (size_t)(kt * 64 + r) * EE + d4);
            *(float4*)(&Vs[r][d4]) = vv;
        }
        __syncthreads();

        float s[4][4];
#pragma unroll
        for (int i = 0; i < 4; i++)
#pragma unroll
            for (int j = 0; j < 4; j++) s[i][j] = 0.f;
#pragma unroll
        for (int d = 0; d < 64; d++) {
            float4 a = *(const float4*)(&Qs[d][ty * 4]);
            float4 bb = *(const float4*)(&Ks[d][tx * 4]);
            float av[4] = {a.x, a.y, a.z, a.w};
            float bv[4] = {bb.x, bb.y, bb.z, bb.w};
#pragma unroll
            for (int i = 0; i < 4; i++)
#pragma unroll
                for (int j = 0; j < 4; j++)
                    s[i][j] = fmaf(av[i], bv[j], s[i][j]);
        }

#pragma unroll
        for (int i = 0; i < 4; i++) {
            float mx = fmaxf(fmaxf(s[i][0], s[i][1]), fmaxf(s[i][2], s[i][3]));
            mx *= sc;
#pragma unroll
            for (int off = 1; off < 16; off <<= 1)
                mx = fmaxf(mx, __shfl_xor_sync(0xffffffffu, mx, off));
            float mnew = fmaxf(m[i], mx);
            float corr = __expf(m[i] - mnew);
            float ps = 0.f;
#pragma unroll
            for (int j = 0; j < 4; j++) {
                float p = __expf(fmaf(s[i][j], sc, -mnew));
                Ps[tx * 4 + j][ty * 4 + i] = p;
                ps += p;
            }
#pragma unroll
            for (int off = 1; off < 16; off <<= 1)
                ps += __shfl_xor_sync(0xffffffffu, ps, off);
            l[i] = l[i] * corr + ps;
            m[i] = mnew;
#pragma unroll
            for (int j = 0; j < 4; j++) acc[i][j] *= corr;
        }
        __syncthreads();

#pragma unroll
        for (int k = 0; k < 64; k++) {
            float4 a = *(const float4*)(&Ps[k][ty * 4]);
            float4 bb = *(const float4*)(&Vs[k][tx * 4]);
            float av[4] = {a.x, a.y, a.z, a.w};
            float bv[4] = {bb.x, bb.y, bb.z, bb.w};
#pragma unroll
            for (int i = 0; i < 4; i++)
#pragma unroll
                for (int j = 0; j < 4; j++)
                    acc[i][j] = fmaf(av[i], bv[j], acc[i][j]);
        }
    }

#pragma unroll
    for (int i = 0; i < 4; i++) {
        float inv = 1.f / l[i];
        size_t row = (size_t)(qt * 64 + ty * 4 + i);
        float4 o;
        o.x = acc[i][0] * inv; o.y = acc[i][1] * inv;
        o.z = acc[i][2] * inv; o.w = acc[i][3] * inv;
        *(float4*)(g_O + base + row * EE + tx * 4) = o;
    }
}

// ---------------------------------------------------------------------------
// LayerNorm (unchanged)
// ---------------------------------------------------------------------------
__global__ __launch_bounds__(256) void ln_kernel(
    const float* __restrict__ gamma, const float* __restrict__ beta,
    float* __restrict__ out)
{
    const int row = blockIdx.x;
    const int tid = threadIdx.x;
    const float4 v = *(const float4*)(g_R + (size_t)row * EE + tid * 4);

    float s1 = v.x + v.y + v.z + v.w;
    float s2 = v.x * v.x + v.y * v.y + v.z * v.z + v.w * v.w;

    __shared__ float sh1[8], sh2[8];
#pragma unroll
    for (int off = 16; off > 0; off >>= 1) {
        s1 += __shfl_xor_sync(0xffffffffu, s1, off);
        s2 += __shfl_xor_sync(0xffffffffu, s2, off);
    }
    const int warp = tid >> 5;
    if ((tid & 31) == 0) { sh1[warp] = s1; sh2[warp] = s2; }
    __syncthreads();
    float t1 = 0.f, t2 = 0.f;
#pragma unroll
    for (int w = 0; w < 8; w++) { t1 += sh1[w]; t2 += sh2[w]; }

    const float mean = t1 * (1.0f / EE);
    const float var  = t2 * (1.0f / EE) - mean * mean;
    const float inv  = rsqrtf(var + 1e-6f);

    const float4 g  = *(const float4*)(gamma + tid * 4);
    const float4 bt = *(const float4*)(beta + tid * 4);
    float4 o;
    o.x = (v.x - mean) * inv * g.x + bt.x;
    o.y = (v.y - mean) * inv * g.y + bt.y;
    o.z = (v.z - mean) * inv * g.z + bt.z;
    o.w = (v.w - mean) * inv * g.w + bt.w;
    *(float4*)(out + (size_t)row * EE + tid * 4) = o;
}

// ---------------------------------------------------------------------------
extern "C" void kernel_launch(void* const* d_in, const int* in_sizes, int n_in,
                              void* d_out, int out_size)
{
    const float* X     = (const float*)d_in[0];
    const float* gQ    = (const float*)d_in[1];
    const float* gK    = (const float*)d_in[2];
    const float* Wq    = (const float*)d_in[3];
    const float* Wk    = (const float*)d_in[4];
    const float* Wv    = (const float*)d_in[5];
    const float* Wo    = (const float*)d_in[6];
    const float* gamma = (const float*)d_in[7];
    const float* beta  = (const float*)d_in[8];
    float* out = (float*)d_out;

    cudaFuncSetAttribute(gemm_bf16x2_kernel,
                         cudaFuncAttributeMaxDynamicSharedMemorySize, GEMM_SMEM);
    cudaFuncSetAttribute(attn_kernel,
                         cudaFuncAttributeMaxDynamicSharedMemorySize, ATTN_SMEM);

    dim3 gemm_grid(EE / 128, M_TOT / 128);   // (8, 64)

    gemm_bf16x2_kernel<<<gemm_grid, 256, GEMM_SMEM>>>(X, Wq, gQ, 0);
    gemm_bf16x2_kernel<<<gemm_grid, 256, GEMM_SMEM>>>(X, Wk, gK, 1);
    gemm_bf16x2_kernel<<<gemm_grid, 256, GEMM_SMEM>>>(X, Wv, nullptr, 2);

    attn_kernel<<<dim3(SS / 64, HH, BB), 256, ATTN_SMEM>>>();

    gemm_bf16x2_kernel<<<gemm_grid, 256, GEMM_SMEM>>>(nullptr, Wo, X, 3);
    ln_kernel<<<M_TOT, 256>>>(gamma, beta, out);
}

// round 4
// speedup vs baseline: 2.1114x; 1.7084x over previous
#include <cuda_runtime.h>
#include <cuda_bf16.h>
#include <stdint.h>

#define BB 8
#define SS 1024
#define EE 1024
#define HH 16
#define DD 64
#define M_TOT 8192
#define NELEM ((size_t)M_TOT * EE)   /* 8388608 */

// ---------------- scratch (device globals; no allocations) ----------------
__device__ __nv_bfloat16 g_Xh[NELEM], g_Xl[NELEM];
__device__ __nv_bfloat16 g_Wth[4 * 1048576], g_Wtl[4 * 1048576];  // [N][K] K-major
__device__ __nv_bfloat16 g_Qh[NELEM], g_Ql[NELEM];   // [token][ch], gate*2*0.125 folded
__device__ __nv_bfloat16 g_Kh[NELEM], g_Kl[NELEM];   // [token][ch], gate*2 folded
__device__ __nv_bfloat16 g_Vth[NELEM], g_Vtl[NELEM]; // [(b*H+h)*64+d][s] transposed
__device__ __nv_bfloat16 g_Oh[NELEM], g_Ol[NELEM];   // attention output, bf16 split
__device__ float g_R[NELEM];

// ---------------- helpers ----------------
__device__ __forceinline__ void mma_bf16(float* c, const uint32_t* a,
                                         uint32_t b0, uint32_t b1) {
    asm volatile(
        "mma.sync.aligned.m16n8k16.row.col.f32.bf16.bf16.f32 "
        "{%0,%1,%2,%3}, {%4,%5,%6,%7}, {%8,%9}, {%0,%1,%2,%3};"
        : "+f"(c[0]), "+f"(c[1]), "+f"(c[2]), "+f"(c[3])
        : "r"(a[0]), "r"(a[1]), "r"(a[2]), "r"(a[3]), "r"(b0), "r"(b1));
}

__device__ __forceinline__ void split2(float x, float y, uint32_t& h, uint32_t& l) {
    __nv_bfloat162 hh = __floats2bfloat162_rn(x, y);
    __nv_bfloat162 ll = __floats2bfloat162_rn(x - __bfloat162float(hh.x),
                                              y - __bfloat162float(hh.y));
    h = *(uint32_t*)&hh;
    l = *(uint32_t*)&ll;
}

__device__ __forceinline__ void split1(float x, __nv_bfloat16& h, __nv_bfloat16& l) {
    h = __float2bfloat16(x);
    l = __float2bfloat16(x - __bfloat162float(h));
}

// ---------------- prep: split X into bf16 hi/lo ----------------
__global__ __launch_bounds__(256) void prep_x_kernel(const float* __restrict__ X)
{
    size_t i = ((size_t)blockIdx.x * 256 + threadIdx.x) * 4;
    float4 v = *(const float4*)(X + i);
    uint32_t h01, l01, h23, l23;
    split2(v.x, v.y, h01, l01);
    split2(v.z, v.w, h23, l23);
    *(uint32_t*)(g_Xh + i)     = h01;
    *(uint32_t*)(g_Xh + i + 2) = h23;
    *(uint32_t*)(g_Xl + i)     = l01;
    *(uint32_t*)(g_Xl + i + 2) = l23;
}

// ---------------- prep: weights -> K-major bf16 hi/lo ----------------
// which 0..2: W is [K][N] -> transpose to [N][K]. which 3: Wo already [N][K].
__global__ __launch_bounds__(256) void prep_w_kernel(
    const float* __restrict__ Wq, const float* __restrict__ Wk,
    const float* __restrict__ Wv, const float* __restrict__ Wo)
{
    const int which = blockIdx.z;
    const float* W = (which == 0) ? Wq : (which == 1) ? Wk : (which == 2) ? Wv : Wo;
    __nv_bfloat16* Oh = g_Wth + (size_t)which * 1048576;
    __nv_bfloat16* Ol = g_Wtl + (size_t)which * 1048576;

    __shared__ float tile[32][33];
    const int tx = threadIdx.x, ty = threadIdx.y;   // block (32,8)
    const int n0 = blockIdx.x * 32, k0 = blockIdx.y * 32;

    if (which < 3) {
#pragma unroll
        for (int i = 0; i < 4; i++)
            tile[ty + 8 * i][tx] = W[(size_t)(k0 + ty + 8 * i) * EE + n0 + tx];
        __syncthreads();
#pragma unroll
        for (int i = 0; i < 4; i++) {
            float v = tile[tx][ty + 8 * i];
            __nv_bfloat16 h, l;
            split1(v, h, l);
            size_t o = (size_t)(n0 + ty + 8 * i) * EE + k0 + tx;
            Oh[o] = h; Ol[o] = l;
        }
    } else {
#pragma unroll
        for (int i = 0; i < 4; i++) {
            size_t o = (size_t)(n0 + ty + 8 * i) * EE + k0 + tx;
            float v = W[o];
            __nv_bfloat16 h, l;
            split1(v, h, l);
            Oh[o] = h; Ol[o] = l;
        }
    }
}

// ---------------- GEMM: pre-split bf16 operands, mma.sync 3-term ----------------
// C tile 128x128, BK=32, 8 warps (4M x 2N), double-buffered smem.
// mode 0: Q = X@Wq * gate*0.25  -> g_Qh/g_Ql
// mode 1: K = X@Wk * gate*2    -> g_Kh/g_Kl
// mode 2: V = X@Wv             -> g_Vth/g_Vtl (transposed)
// mode 3: R = O@Wo^T + X       -> g_R (fp32)
#define GROW 80                            /* bytes per smem row: 40 bf16 (32+8 pad) */
#define GTILE (128 * GROW)                 /* 10240 */
#define GSTAGE (4 * GTILE)                 /* Ah, Al, Bh, Bl = 40960 */
#define GEMM_SMEM (2 * GSTAGE)             /* 81920 */

__global__ __launch_bounds__(256, 1) void gemm_kernel(
    const float* __restrict__ Aux, int mode)
{
    extern __shared__ char smb[];

    const __nv_bfloat16* Ah = (mode == 3) ? g_Oh : g_Xh;
    const __nv_bfloat16* Al = (mode == 3) ? g_Ol : g_Xl;
    const __nv_bfloat16* Bh = g_Wth + (size_t)mode * 1048576;
    const __nv_bfloat16* Bl = g_Wtl + (size_t)mode * 1048576;

    const int tid = threadIdx.x;
    const int wid = tid >> 5;
    const int lane = tid & 31;
    const int g = lane >> 2;
    const int tig = lane & 3;
    const int wm = wid >> 1;
    const int wn = wid & 1;
    const int colBase = blockIdx.x * 128;
    const int rowBase = blockIdx.y * 128;

    float c[2][8][4];
#pragma unroll
    for (int mt = 0; mt < 2; mt++)
#pragma unroll
        for (int nt = 0; nt < 8; nt++)
#pragma unroll
            for (int r = 0; r < 4; r++) c[mt][nt][r] = 0.f;

    uint4 rah[2], ral[2], rbh[2], rbl[2];

    auto ldg = [&](int kt) {
#pragma unroll
        for (int i = 0; i < 2; i++) {
            int ch = tid * 2 + i;          // 0..511
            int r = ch >> 2;
            int c8 = (ch & 3) * 8;
            size_t ao = (size_t)(rowBase + r) * EE + kt * 32 + c8;
            size_t bo = (size_t)(colBase + r) * EE + kt * 32 + c8;
            rah[i] = *(const uint4*)(Ah + ao);
            ral[i] = *(const uint4*)(Al + ao);
            rbh[i] = *(const uint4*)(Bh + bo);
            rbl[i] = *(const uint4*)(Bl + bo);
        }
    };
    auto sts = [&](int buf) {
        char* bp = smb + buf * GSTAGE;
#pragma unroll
        for (int i = 0; i < 2; i++) {
            int ch = tid * 2 + i;
            int off = (ch >> 2) * GROW + (ch & 3) * 16;
            *(uint4*)(bp + off)             = rah[i];
            *(uint4*)(bp + GTILE + off)     = ral[i];
            *(uint4*)(bp + 2 * GTILE + off) = rbh[i];
            *(uint4*)(bp + 3 * GTILE + off) = rbl[i];
        }
    };

    ldg(0);
    sts(0);
    __syncthreads();

    for (int kt = 0; kt < 32; kt++) {
        if (kt < 31) ldg(kt + 1);
        const char* bp = smb + (kt & 1) * GSTAGE;

#pragma unroll
        for (int ks = 0; ks < 2; ks++) {
            uint32_t ah[2][4], al[2][4];
#pragma unroll
            for (int mt = 0; mt < 2; mt++) {
                const char* ar = bp + (wm * 32 + mt * 16 + g) * GROW + ks * 32 + tig * 4;
                ah[mt][0] = *(const uint32_t*)ar;
                ah[mt][1] = *(const uint32_t*)(ar + 8 * GROW);
                ah[mt][2] = *(const uint32_t*)(ar + 16);
                ah[mt][3] = *(const uint32_t*)(ar + 8 * GROW + 16);
                al[mt][0] = *(const uint32_t*)(ar + GTILE);
                al[mt][1] = *(const uint32_t*)(ar + GTILE + 8 * GROW);
                al[mt][2] = *(const uint32_t*)(ar + GTILE + 16);
                al[mt][3] = *(const uint32_t*)(ar + GTILE + 8 * GROW + 16);
            }
#pragma unroll
            for (int nt = 0; nt < 8; nt++) {
                const char* br = bp + 2 * GTILE + (wn * 64 + nt * 8 + g) * GROW
                               + ks * 32 + tig * 4;
                uint32_t b0h = *(const uint32_t*)br;
                uint32_t b1h = *(const uint32_t*)(br + 16);
                uint32_t b0l = *(const uint32_t*)(br + GTILE);
                uint32_t b1l = *(const uint32_t*)(br + GTILE + 16);
#pragma unroll
                for (int mt = 0; mt < 2; mt++) {
                    mma_bf16(c[mt][nt], ah[mt], b0h, b1h);
                    mma_bf16(c[mt][nt], ah[mt], b0l, b1l);
                    mma_bf16(c[mt][nt], al[mt], b0h, b1h);
                }
            }
        }
        if (kt < 31) {
            sts((kt + 1) & 1);
            __syncthreads();
        }
    }

    // ---- epilogues ----
    const int batch = rowBase / SS;
    if (mode <= 1) {
        __nv_bfloat16* Oh = (mode == 0) ? g_Qh : g_Kh;
        __nv_bfloat16* Ol = (mode == 0) ? g_Ql : g_Kl;
        const float sc = (mode == 0) ? 0.25f : 2.0f;   // gate*2 (*0.125 for Q)
#pragma unroll
        for (int mt = 0; mt < 2; mt++) {
            size_t row0 = (size_t)rowBase + wm * 32 + mt * 16 + g;
#pragma unroll
            for (int nt = 0; nt < 8; nt++) {
                int col = colBase + wn * 64 + nt * 8 + 2 * tig;
                float2 gv = *(const float2*)(Aux + (size_t)batch * EE + col);
                float gx = gv.x * sc, gy = gv.y * sc;
                uint32_t h, l;
                split2(c[mt][nt][0] * gx, c[mt][nt][1] * gy, h, l);
                *(uint32_t*)(Oh + row0 * EE + col) = h;
                *(uint32_t*)(Ol + row0 * EE + col) = l;
                split2(c[mt][nt][2] * gx, c[mt][nt][3] * gy, h, l);
                *(uint32_t*)(Oh + (row0 + 8) * EE + col) = h;
                *(uint32_t*)(Ol + (row0 + 8) * EE + col) = l;
            }
        }
    } else if (mode == 2) {
#pragma unroll
        for (int mt = 0; mt < 2; mt++) {
            int row0 = rowBase + wm * 32 + mt * 16 + g;
            int s = row0 - batch * SS;
#pragma unroll
            for (int nt = 0; nt < 8; nt++) {
                int col = colBase + wn * 64 + nt * 8 + 2 * tig;
                int hh = col >> 6, d = col & 63;
                size_t vb = ((size_t)(batch * HH + hh) * 64 + d) * SS + s;
                __nv_bfloat16 h, l;
                split1(c[mt][nt][0], h, l); g_Vth[vb] = h;          g_Vtl[vb] = l;
                split1(c[mt][nt][1], h, l); g_Vth[vb + SS] = h;     g_Vtl[vb + SS] = l;
                split1(c[mt][nt][2], h, l); g_Vth[vb + 8] = h;      g_Vtl[vb + 8] = l;
                split1(c[mt][nt][3], h, l); g_Vth[vb + SS + 8] = h; g_Vtl[vb + SS + 8] = l;
            }
        }
    } else {
#pragma unroll
        for (int mt = 0; mt < 2; mt++) {
            size_t row0 = (size_t)rowBase + wm * 32 + mt * 16 + g;
#pragma unroll
            for (int nt = 0; nt < 8; nt++) {
                int col = colBase + wn * 64 + nt * 8 + 2 * tig;
                float2 x0 = *(const float2*)(Aux + row0 * EE + col);
                float2 x1 = *(const float2*)(Aux + (row0 + 8) * EE + col);
                *(float2*)(g_R + row0 * EE + col) =
                    make_float2(c[mt][nt][0] + x0.x, c[mt][nt][1] + x0.y);
                *(float2*)(g_R + (row0 + 8) * EE + col) =
                    make_float2(c[mt][nt][2] + x1.x, c[mt][nt][3] + x1.y);
            }
        }
    }
}

// ---------------- tensor-core flash attention ----------------
// CTA = (qt, h, b): 128 q-rows, 8 warps x 16 rows. Key tiles of 64.
// K/V hi/lo double-buffered in smem; Q frags in registers; P stays in registers.
#define AROW 144                            /* 72 bf16 per smem row (64 + 8 pad) */
#define ATILE (64 * AROW)                   /* 9216 */
#define ABUF (4 * ATILE)                    /* Kh, Kl, Vh, Vl = 36864 */
#define ATTN_SMEM (2 * ABUF)                /* 73728 */

__global__ __launch_bounds__(256, 1) void attn_kernel()
{
    extern __shared__ char smb[];

    const int qt = blockIdx.x;
    const int h  = blockIdx.y;
    const int b  = blockIdx.z;
    const int tid = threadIdx.x;
    const int wid = tid >> 5;
    const int lane = tid & 31;
    const int g = lane >> 2;
    const int tig = lane & 3;

    // ---- Q fragments, hi/lo, direct from gmem (held all kernel) ----
    uint32_t qh[4][4], ql[4][4];
    {
        size_t rg = (size_t)(b * SS + qt * 128 + wid * 16 + g);
        const __nv_bfloat16* ph = g_Qh + rg * EE + h * 64;
        const __nv_bfloat16* pl = g_Ql + rg * EE + h * 64;
#pragma unroll
        for (int ks = 0; ks < 4; ks++) {
            int c0 = ks * 16 + 2 * tig;
            qh[ks][0] = *(const uint32_t*)(ph + c0);
            qh[ks][1] = *(const uint32_t*)(ph + 8 * EE + c0);
            qh[ks][2] = *(const uint32_t*)(ph + c0 + 8);
            qh[ks][3] = *(const uint32_t*)(ph + 8 * EE + c0 + 8);
            ql[ks][0] = *(const uint32_t*)(pl + c0);
            ql[ks][1] = *(const uint32_t*)(pl + 8 * EE + c0);
            ql[ks][2] = *(const uint32_t*)(pl + c0 + 8);
            ql[ks][3] = *(const uint32_t*)(pl + 8 * EE + c0 + 8);
        }
    }

    float acc[8][4];
#pragma unroll
    for (int j = 0; j < 8; j++)
#pragma unroll
        for (int r = 0; r < 4; r++) acc[j][r] = 0.f;
    float m0 = -1e30f, m1 = -1e30f, l0 = 0.f, l1 = 0.f;

    uint4 rkh[2], rkl[2], rvh[2], rvl[2];
    const size_t kbase0 = ((size_t)b * SS) * EE + h * 64;
    const size_t vbase0 = ((size_t)(b * HH + h) * 64) * SS;

    auto ldt = [&](int kt) {
#pragma unroll
        for (int i = 0; i < 2; i++) {
            int ch = tid * 2 + i;          // 0..511
            int r = ch >> 3;
            int c8 = (ch & 7) * 8;
            size_t ko = kbase0 + (size_t)(kt * 64 + r) * EE + c8;
            size_t vo = vbase0 + (size_t)r * SS + kt * 64 + c8;
            rkh[i] = *(const uint4*)(g_Kh + ko);
            rkl[i] = *(const uint4*)(g_Kl + ko);
            rvh[i] = *(const uint4*)(g_Vth + vo);
            rvl[i] = *(const uint4*)(g_Vtl + vo);
        }
    };
    auto stt = [&](int buf) {
        char* bp = smb + buf * ABUF;
#pragma unroll
        for (int i = 0; i < 2; i++) {
            int ch = tid * 2 + i;
            int off = (ch >> 3) * AROW + (ch & 7) * 16;
            *(uint4*)(bp + off)             = rkh[i];
            *(uint4*)(bp + ATILE + off)     = rkl[i];
            *(uint4*)(bp + 2 * ATILE + off) = rvh[i];
            *(uint4*)(bp + 3 * ATILE + off) = rvl[i];
        }
    };

    ldt(0);
    stt(0);
    __syncthreads();

    for (int kt = 0; kt < 16; kt++) {
        if (kt < 15) ldt(kt + 1);
        const char* bp = smb + (kt & 1) * ABUF;

        // ---- scores: c[j] = Q . K^T (pre-scaled by 1/8 via Q) ----
        float c[8][4];
#pragma unroll
        for (int j = 0; j < 8; j++)
#pragma unroll
            for (int r = 0; r < 4; r++) c[j][r] = 0.f;

#pragma unroll
        for (int ks = 0; ks < 4; ks++) {
#pragma unroll
            for (int j = 0; j < 8; j++) {
                const char* kr = bp + (j * 8 + g) * AROW + ks * 32 + tig * 4;
                uint32_t b0h = *(const uint32_t*)kr;
                uint32_t b1h = *(const uint32_t*)(kr + 16);
                uint32_t b0l = *(const uint32_t*)(kr + ATILE);
                uint32_t b1l = *(const uint32_t*)(kr + ATILE + 16);
                mma_bf16(c[j], qh[ks], b0h, b1h);
                mma_bf16(c[j], qh[ks], b0l, b1l);
                mma_bf16(c[j], ql[ks], b0h, b1h);
            }
        }

        // ---- online softmax in C-fragment registers ----
        float mx0 = -1e30f, mx1 = -1e30f;
#pragma unroll
        for (int j = 0; j < 8; j++) {
            mx0 = fmaxf(mx0, fmaxf(c[j][0], c[j][1]));
            mx1 = fmaxf(mx1, fmaxf(c[j][2], c[j][3]));
        }
        mx0 = fmaxf(mx0, __shfl_xor_sync(0xffffffffu, mx0, 1));
        mx0 = fmaxf(mx0, __shfl_xor_sync(0xffffffffu, mx0, 2));
        mx1 = fmaxf(mx1, __shfl_xor_sync(0xffffffffu, mx1, 1));
        mx1 = fmaxf(mx1, __shfl_xor_sync(0xffffffffu, mx1, 2));
        float mn0 = fmaxf(m0, mx0), mn1 = fmaxf(m1, mx1);
        float cr0 = __expf(m0 - mn0), cr1 = __expf(m1 - mn1);
        float s0 = 0.f, s1 = 0.f;
#pragma unroll
        for (int j = 0; j < 8; j++) {
            c[j][0] = __expf(c[j][0] - mn0);
            c[j][1] = __expf(c[j][1] - mn0);
            c[j][2] = __expf(c[j][2] - mn1);
            c[j][3] = __expf(c[j][3] - mn1);
            s0 += c[j][0] + c[j][1];
            s1 += c[j][2] + c[j][3];
        }
        s0 += __shfl_xor_sync(0xffffffffu, s0, 1);
        s0 += __shfl_xor_sync(0xffffffffu, s0, 2);
        s1 += __shfl_xor_sync(0xffffffffu, s1, 1);
        s1 += __shfl_xor_sync(0xffffffffu, s1, 2);
        l0 = l0 * cr0 + s0;
        l1 = l1 * cr1 + s1;
        m0 = mn0; m1 = mn1;
#pragma unroll
        for (int j = 0; j < 8; j++) {
            acc[j][0] *= cr0; acc[j][1] *= cr0;
            acc[j][2] *= cr1; acc[j][3] *= cr1;
        }

        // ---- PV: P fragments packed in registers (no smem) ----
#pragma unroll
        for (int ks = 0; ks < 4; ks++) {
            uint32_t ph[4], pl[4];
            split2(c[2 * ks][0],     c[2 * ks][1],     ph[0], pl[0]);
            split2(c[2 * ks][2],     c[2 * ks][3],     ph[1], pl[1]);
            split2(c[2 * ks + 1][0], c[2 * ks + 1][1], ph[2], pl[2]);
            split2(c[2 * ks + 1][2], c[2 * ks + 1][3], ph[3], pl[3]);
#pragma unroll
            for (int j = 0; j < 8; j++) {
                const char* vr = bp + 2 * ATILE + (j * 8 + g) * AROW + ks * 32 + tig * 4;
                uint32_t b0h = *(const uint32_t*)vr;
                uint32_t b1h = *(const uint32_t*)(vr + 16);
                uint32_t b0l = *(const uint32_t*)(vr + ATILE);
                uint32_t b1l = *(const uint32_t*)(vr + ATILE + 16);
                mma_bf16(acc[j], ph, b0h, b1h);
                mma_bf16(acc[j], ph, b0l, b1l);
                mma_bf16(acc[j], pl, b0h, b1h);
            }
        }

        if (kt < 15) {
            stt((kt + 1) & 1);
            __syncthreads();
        }
    }

    // ---- epilogue: O = acc/l, write bf16 hi/lo ----
    float i0 = 1.f / l0, i1 = 1.f / l1;
    size_t rg = (size_t)(b * SS + qt * 128 + wid * 16 + g);
#pragma unroll
    for (int j = 0; j < 8; j++) {
        int col = h * 64 + j * 8 + 2 * tig;
        uint32_t hh, ll;
        split2(acc[j][0] * i0, acc[j][1] * i0, hh, ll);
        *(uint32_t*)(g_Oh + rg * EE + col) = hh;
        *(uint32_t*)(g_Ol + rg * EE + col) = ll;
        split2(acc[j][2] * i1, acc[j][3] * i1, hh, ll);
        *(uint32_t*)(g_Oh + (rg + 8) * EE + col) = hh;
        *(uint32_t*)(g_Ol + (rg + 8) * EE + col) = ll;
    }
}

// ---------------- LayerNorm ----------------
__global__ __launch_bounds__(256) void ln_kernel(
    const float* __restrict__ gamma, const float* __restrict__ beta,
    float* __restrict__ out)
{
    const int row = blockIdx.x;
    const int tid = threadIdx.x;
    const float4 v = *(const float4*)(g_R + (size_t)row * EE + tid * 4);

    float s1 = v.x + v.y + v.z + v.w;
    float s2 = v.x * v.x + v.y * v.y + v.z * v.z + v.w * v.w;

    __shared__ float sh1[8], sh2[8];
#pragma unroll
    for (int off = 16; off > 0; off >>= 1) {
        s1 += __shfl_xor_sync(0xffffffffu, s1, off);
        s2 += __shfl_xor_sync(0xffffffffu, s2, off);
    }
    const int warp = tid >> 5;
    if ((tid & 31) == 0) { sh1[warp] = s1; sh2[warp] = s2; }
    __syncthreads();
    float t1 = 0.f, t2 = 0.f;
#pragma unroll
    for (int w = 0; w < 8; w++) { t1 += sh1[w]; t2 += sh2[w]; }

    const float mean = t1 * (1.0f / EE);
    const float var  = t2 * (1.0f / EE) - mean * mean;
    const float inv  = rsqrtf(var + 1e-6f);

    const float4 gmv = *(const float4*)(gamma + tid * 4);
    const float4 btv = *(const float4*)(beta + tid * 4);
    float4 o;
    o.x = (v.x - mean) * inv * gmv.x + btv.x;
    o.y = (v.y - mean) * inv * gmv.y + btv.y;
    o.z = (v.z - mean) * inv * gmv.z + btv.z;
    o.w = (v.w - mean) * inv * gmv.w + btv.w;
    *(float4*)(out + (size_t)row * EE + tid * 4) = o;
}

// ---------------------------------------------------------------------------
extern "C" void kernel_launch(void* const* d_in, const int* in_sizes, int n_in,
                              void* d_out, int out_size)
{
    const float* X     = (const float*)d_in[0];
    const float* gQ    = (const float*)d_in[1];
    const float* gK    = (const float*)d_in[2];
    const float* Wq    = (const float*)d_in[3];
    const float* Wk    = (const float*)d_in[4];
    const float* Wv    = (const float*)d_in[5];
    const float* Wo    = (const float*)d_in[6];
    const float* gamma = (const float*)d_in[7];
    const float* beta  = (const float*)d_in[8];
    float* out = (float*)d_out;

    cudaFuncSetAttribute(gemm_kernel,
                         cudaFuncAttributeMaxDynamicSharedMemorySize, GEMM_SMEM);
    cudaFuncSetAttribute(attn_kernel,
                         cudaFuncAttributeMaxDynamicSharedMemorySize, ATTN_SMEM);

    prep_x_kernel<<<NELEM / 1024, 256>>>(X);
    prep_w_kernel<<<dim3(32, 32, 4), dim3(32, 8)>>>(Wq, Wk, Wv, Wo);

    dim3 gemm_grid(EE / 128, M_TOT / 128);   // (8, 64)
    gemm_kernel<<<gemm_grid, 256, GEMM_SMEM>>>(gQ, 0);
    gemm_kernel<<<gemm_grid, 256, GEMM_SMEM>>>(gK, 1);
    gemm_kernel<<<gemm_grid, 256, GEMM_SMEM>>>(nullptr, 2);

    attn_kernel<<<dim3(8, HH, BB), 256, ATTN_SMEM>>>();

    gemm_kernel<<<gemm_grid, 256, GEMM_SMEM>>>(X, 3);
    ln_kernel<<<M_TOT, 256>>>(gamma, beta, out);
}

// round 5
// speedup vs baseline: 2.4613x; 1.1657x over previous
#include <cuda_runtime.h>
#include <cuda_bf16.h>
#include <stdint.h>

#define BB 8
#define SS 1024
#define EE 1024
#define HH 16
#define M_TOT 8192
#define NELEM ((size_t)M_TOT * EE)   /* 8388608 */

// ---------------- scratch (device globals; no allocations) ----------------
__device__ __nv_bfloat16 g_Xh[NELEM], g_Xl[NELEM];
__device__ __nv_bfloat16 g_Wth[4 * 1048576], g_Wtl[4 * 1048576];  // [N][K] K-major
__device__ __nv_bfloat16 g_Qh[NELEM], g_Ql[NELEM];   // gate*2*0.125 folded
__device__ __nv_bfloat16 g_Kh[NELEM], g_Kl[NELEM];   // gate*2 folded
__device__ __nv_bfloat16 g_Vth[NELEM], g_Vtl[NELEM]; // [(b*H+h)*64+d][s]
__device__ __nv_bfloat16 g_Oh[NELEM], g_Ol[NELEM];
__device__ float g_R[NELEM];

// ---------------- helpers ----------------
__device__ __forceinline__ void mma_bf16(float* c, const uint32_t* a,
                                         uint32_t b0, uint32_t b1) {
    asm volatile(
        "mma.sync.aligned.m16n8k16.row.col.f32.bf16.bf16.f32 "
        "{%0,%1,%2,%3}, {%4,%5,%6,%7}, {%8,%9}, {%0,%1,%2,%3};"
        : "+f"(c[0]), "+f"(c[1]), "+f"(c[2]), "+f"(c[3])
        : "r"(a[0]), "r"(a[1]), "r"(a[2]), "r"(a[3]), "r"(b0), "r"(b1));
}

__device__ __forceinline__ void ldsm4(uint32_t* r, uint32_t addr) {
    asm volatile("ldmatrix.sync.aligned.m8n8.x4.shared.b16 {%0,%1,%2,%3}, [%4];"
                 : "=r"(r[0]), "=r"(r[1]), "=r"(r[2]), "=r"(r[3]) : "r"(addr));
}

__device__ __forceinline__ void cp16(uint32_t s, const void* g) {
    asm volatile("cp.async.cg.shared.global [%0], [%1], 16;" :: "r"(s), "l"(g));
}
#define CP_COMMIT asm volatile("cp.async.commit_group;" ::: "memory")
#define CP_WAIT(n) asm volatile("cp.async.wait_group %0;" :: "n"(n) : "memory")

__device__ __forceinline__ uint32_t smem_u32(const void* p) {
    uint32_t a;
    asm("{ .reg .u64 t; cvta.to.shared.u64 t, %1; cvt.u32.u64 %0, t; }"
        : "=r"(a) : "l"(p));
    return a;
}

__device__ __forceinline__ void split2(float x, float y, uint32_t& h, uint32_t& l) {
    __nv_bfloat162 hh = __floats2bfloat162_rn(x, y);
    __nv_bfloat162 ll = __floats2bfloat162_rn(x - __bfloat162float(hh.x),
                                              y - __bfloat162float(hh.y));
    h = *(uint32_t*)&hh;
    l = *(uint32_t*)&ll;
}

__device__ __forceinline__ void split1(float x, __nv_bfloat16& h, __nv_bfloat16& l) {
    h = __float2bfloat16(x);
    l = __float2bfloat16(x - __bfloat162float(h));
}

// ---------------- prep: split X ----------------
__global__ __launch_bounds__(256) void prep_x_kernel(const float* __restrict__ X)
{
    size_t i = ((size_t)blockIdx.x * 256 + threadIdx.x) * 4;
    float4 v = *(const float4*)(X + i);
    uint32_t h01, l01, h23, l23;
    split2(v.x, v.y, h01, l01);
    split2(v.z, v.w, h23, l23);
    *(uint32_t*)(g_Xh + i)     = h01;
    *(uint32_t*)(g_Xh + i + 2) = h23;
    *(uint32_t*)(g_Xl + i)     = l01;
    *(uint32_t*)(g_Xl + i + 2) = l23;
}

// ---------------- prep: weights -> K-major bf16 hi/lo ----------------
__global__ __launch_bounds__(256) void prep_w_kernel(
    const float* __restrict__ Wq, const float* __restrict__ Wk,
    const float* __restrict__ Wv, const float* __restrict__ Wo)
{
    const int which = blockIdx.z;
    const float* W = (which == 0) ? Wq : (which == 1) ? Wk : (which == 2) ? Wv : Wo;
    __nv_bfloat16* Oh = g_Wth + (size_t)which * 1048576;
    __nv_bfloat16* Ol = g_Wtl + (size_t)which * 1048576;

    __shared__ float tile[32][33];
    const int tx = threadIdx.x, ty = threadIdx.y;
    const int n0 = blockIdx.x * 32, k0 = blockIdx.y * 32;

    if (which < 3) {
#pragma unroll
        for (int i = 0; i < 4; i++)
            tile[ty + 8 * i][tx] = W[(size_t)(k0 + ty + 8 * i) * EE + n0 + tx];
        __syncthreads();
#pragma unroll
        for (int i = 0; i < 4; i++) {
            float v = tile[tx][ty + 8 * i];
            __nv_bfloat16 h, l;
            split1(v, h, l);
            size_t o = (size_t)(n0 + ty + 8 * i) * EE + k0 + tx;
            Oh[o] = h; Ol[o] = l;
        }
    } else {
#pragma unroll
        for (int i = 0; i < 4; i++) {
            size_t o = (size_t)(n0 + ty + 8 * i) * EE + k0 + tx;
            float v = W[o];
            __nv_bfloat16 h, l;
            split1(v, h, l);
            Oh[o] = h; Ol[o] = l;
        }
    }
}

// ---------------- GEMM: cp.async 3-stage + ldmatrix + mma.sync 3-term ----------
// mode 0: Q = X@Wq * gate*0.25 -> g_Qh/l   (grid.z=0)
// mode 1: K = X@Wk * gate*2    -> g_Kh/l   (grid.z=1)
// mode 2: V = X@Wv             -> g_Vth/l  (grid.z=2, transposed)
// mode 3: R = O@Wo^T + X       -> g_R
#define GROW 80                            /* 64B data + 16 pad */
#define GTILE (128 * GROW)                 /* 10240 */
#define GSTAGE (4 * GTILE)                 /* Ah, Al, Bh, Bl = 40960 */
#define GEMM_SMEM (3 * GSTAGE)             /* 122880 */

__global__ __launch_bounds__(256, 1) void gemm_kernel(
    const float* __restrict__ AuxQ, const float* __restrict__ AuxK,
    const float* __restrict__ AuxX, int modeBase)
{
    extern __shared__ char smb[];
    const uint32_t sbase = smem_u32(smb);

    const int mode = modeBase + blockIdx.z;
    const __nv_bfloat16* Ah = (mode == 3) ? g_Oh : g_Xh;
    const __nv_bfloat16* Al = (mode == 3) ? g_Ol : g_Xl;
    const __nv_bfloat16* Bhp = g_Wth + (size_t)mode * 1048576;
    const __nv_bfloat16* Blp = g_Wtl + (size_t)mode * 1048576;

    const int tid = threadIdx.x;
    const int wid = tid >> 5;
    const int lane = tid & 31;
    const int g = lane >> 2;
    const int tig = lane & 3;
    const int wm = wid >> 1;
    const int wn = wid & 1;
    const int colBase = blockIdx.x * 128;
    const int rowBase = blockIdx.y * 128;

    float c[2][8][4];
#pragma unroll
    for (int mt = 0; mt < 2; mt++)
#pragma unroll
        for (int nt = 0; nt < 8; nt++)
#pragma unroll
            for (int r = 0; r < 4; r++) c[mt][nt][r] = 0.f;

    // ldmatrix lane addresses
    const uint32_t aLane = (uint32_t)(wm * 32 + (lane & 7) + ((lane >> 3) & 1) * 8) * GROW
                         + ((lane >> 4) & 1) * 16;
    const uint32_t bLane = (uint32_t)(wn * 64 + (lane & 7) + ((lane >> 4) & 1) * 8) * GROW
                         + ((lane >> 3) & 1) * 16;

    auto issue = [&](int kt, int stage) {
        uint32_t sb = sbase + stage * GSTAGE;
#pragma unroll
        for (int i = 0; i < 2; i++) {
            int ch = tid * 2 + i;               // 0..511
            int r = ch >> 2;                    // 0..127
            int cb = (ch & 3) * 16;             // byte chunk in 64B row
            size_t ao = (size_t)(rowBase + r) * EE + kt * 32 + (ch & 3) * 8;
            size_t bo = (size_t)(colBase + r) * EE + kt * 32 + (ch & 3) * 8;
            uint32_t off = r * GROW + cb;
            cp16(sb + off,             Ah + ao);
            cp16(sb + GTILE + off,     Al + ao);
            cp16(sb + 2 * GTILE + off, Bhp + bo);
            cp16(sb + 3 * GTILE + off, Blp + bo);
        }
        CP_COMMIT;
    };

    issue(0, 0);
    issue(1, 1);

    for (int kt = 0; kt < 32; kt++) {
        if (kt < 31) { CP_WAIT(1); } else { CP_WAIT(0); }
        __syncthreads();
        if (kt + 2 < 32) issue(kt + 2, (kt + 2) % 3);

        const uint32_t sb = sbase + (kt % 3) * GSTAGE;
        const uint32_t aOff = sb + aLane;
        const uint32_t bOff = sb + 2 * GTILE + bLane;

#pragma unroll
        for (int ks = 0; ks < 2; ks++) {
            uint32_t ah[2][4], al[2][4];
            ldsm4(ah[0], aOff + ks * 32);
            ldsm4(ah[1], aOff + 16 * GROW + ks * 32);
            ldsm4(al[0], aOff + GTILE + ks * 32);
            ldsm4(al[1], aOff + GTILE + 16 * GROW + ks * 32);
#pragma unroll
            for (int p = 0; p < 4; p++) {
                uint32_t bh[4], bl[4];
                ldsm4(bh, bOff + p * 16 * GROW + ks * 32);
                ldsm4(bl, bOff + GTILE + p * 16 * GROW + ks * 32);
#pragma unroll
                for (int mt = 0; mt < 2; mt++) {
                    mma_bf16(c[mt][2 * p],     ah[mt], bh[0], bh[1]);
                    mma_bf16(c[mt][2 * p],     ah[mt], bl[0], bl[1]);
                    mma_bf16(c[mt][2 * p],     al[mt], bh[0], bh[1]);
                    mma_bf16(c[mt][2 * p + 1], ah[mt], bh[2], bh[3]);
                    mma_bf16(c[mt][2 * p + 1], ah[mt], bl[2], bl[3]);
                    mma_bf16(c[mt][2 * p + 1], al[mt], bh[2], bh[3]);
                }
            }
        }
    }

    // ---- epilogues ----
    const int batch = rowBase / SS;
    if (mode <= 1) {
        __nv_bfloat16* Oh = (mode == 0) ? g_Qh : g_Kh;
        __nv_bfloat16* Ol = (mode == 0) ? g_Ql : g_Kl;
        const float sc = (mode == 0) ? 0.25f : 2.0f;
        const float* Aux = (mode == 0) ? AuxQ : AuxK;
#pragma unroll
        for (int mt = 0; mt < 2; mt++) {
            size_t row0 = (size_t)rowBase + wm * 32 + mt * 16 + g;
#pragma unroll
            for (int nt = 0; nt < 8; nt++) {
                int col = colBase + wn * 64 + nt * 8 + 2 * tig;
                float2 gv = *(const float2*)(Aux + (size_t)batch * EE + col);
                float gx = gv.x * sc, gy = gv.y * sc;
                uint32_t h, l;
                split2(c[mt][nt][0] * gx, c[mt][nt][1] * gy, h, l);
                *(uint32_t*)(Oh + row0 * EE + col) = h;
                *(uint32_t*)(Ol + row0 * EE + col) = l;
                split2(c[mt][nt][2] * gx, c[mt][nt][3] * gy, h, l);
                *(uint32_t*)(Oh + (row0 + 8) * EE + col) = h;
                *(uint32_t*)(Ol + (row0 + 8) * EE + col) = l;
            }
        }
    } else if (mode == 2) {
#pragma unroll
        for (int mt = 0; mt < 2; mt++) {
            int row0 = rowBase + wm * 32 + mt * 16 + g;
            int s = row0 - batch * SS;
#pragma unroll
            for (int nt = 0; nt < 8; nt++) {
                int col = colBase + wn * 64 + nt * 8 + 2 * tig;
                int hh = col >> 6, d = col & 63;
                size_t vb = ((size_t)(batch * HH + hh) * 64 + d) * SS + s;
                __nv_bfloat16 h, l;
                split1(c[mt][nt][0], h, l); g_Vth[vb] = h;          g_Vtl[vb] = l;
                split1(c[mt][nt][1], h, l); g_Vth[vb + SS] = h;     g_Vtl[vb + SS] = l;
                split1(c[mt][nt][2], h, l); g_Vth[vb + 8] = h;      g_Vtl[vb + 8] = l;
                split1(c[mt][nt][3], h, l); g_Vth[vb + SS + 8] = h; g_Vtl[vb + SS + 8] = l;
            }
        }
    } else {
#pragma unroll
        for (int mt = 0; mt < 2; mt++) {
            size_t row0 = (size_t)rowBase + wm * 32 + mt * 16 + g;
#pragma unroll
            for (int nt = 0; nt < 8; nt++) {
                int col = colBase + wn * 64 + nt * 8 + 2 * tig;
                float2 x0 = *(const float2*)(AuxX + row0 * EE + col);
                float2 x1 = *(const float2*)(AuxX + (row0 + 8) * EE + col);
                *(float2*)(g_R + row0 * EE + col) =
                    make_float2(c[mt][nt][0] + x0.x, c[mt][nt][1] + x0.y);
                *(float2*)(g_R + (row0 + 8) * EE + col) =
                    make_float2(c[mt][nt][2] + x1.x, c[mt][nt][3] + x1.y);
            }
        }
    }
}

// ---------------- tensor-core flash attention (cp.async + ldmatrix) ----------
#define AROW 144                            /* 128B data + 16 pad */
#define ATILE (64 * AROW)                   /* 9216 */
#define ABUF (4 * ATILE)                    /* Kh, Kl, Vh, Vl = 36864 */
#define ATTN_SMEM (2 * ABUF)                /* 73728 */

__global__ __launch_bounds__(256, 1) void attn_kernel()
{
    extern __shared__ char smb[];
    const uint32_t sbase = smem_u32(smb);

    const int qt = blockIdx.x;
    const int h  = blockIdx.y;
    const int b  = blockIdx.z;
    const int tid = threadIdx.x;
    const int wid = tid >> 5;
    const int lane = tid & 31;
    const int g = lane >> 2;
    const int tig = lane & 3;

    const size_t kbase0 = ((size_t)b * SS) * EE + h * 64;
    const size_t vbase0 = ((size_t)(b * HH + h) * 64) * SS;

    auto issue = [&](int kt, int stage) {
        uint32_t sb = sbase + stage * ABUF;
#pragma unroll
        for (int i = 0; i < 2; i++) {
            int ch = tid * 2 + i;               // 0..511
            int r = ch >> 3;                    // 0..63
            int cb = (ch & 7) * 16;
            int c8 = (ch & 7) * 8;
            size_t ko = kbase0 + (size_t)(kt * 64 + r) * EE + c8;
            size_t vo = vbase0 + (size_t)r * SS + kt * 64 + c8;
            uint32_t off = r * AROW + cb;
            cp16(sb + off,             g_Kh + ko);
            cp16(sb + ATILE + off,     g_Kl + ko);
            cp16(sb + 2 * ATILE + off, g_Vth + vo);
            cp16(sb + 3 * ATILE + off, g_Vtl + vo);
        }
        CP_COMMIT;
    };

    issue(0, 0);

    // ---- Q fragments (held all kernel) ----
    uint32_t qh[4][4], ql[4][4];
    {
        size_t rg = (size_t)(b * SS + qt * 128 + wid * 16 + g);
        const __nv_bfloat16* ph = g_Qh + rg * EE + h * 64;
        const __nv_bfloat16* pl = g_Ql + rg * EE + h * 64;
#pragma unroll
        for (int ks = 0; ks < 4; ks++) {
            int c0 = ks * 16 + 2 * tig;
            qh[ks][0] = *(const uint32_t*)(ph + c0);
            qh[ks][1] = *(const uint32_t*)(ph + 8 * EE + c0);
            qh[ks][2] = *(const uint32_t*)(ph + c0 + 8);
            qh[ks][3] = *(const uint32_t*)(ph + 8 * EE + c0 + 8);
            ql[ks][0] = *(const uint32_t*)(pl + c0);
            ql[ks][1] = *(const uint32_t*)(pl + 8 * EE + c0);
            ql[ks][2] = *(const uint32_t*)(pl + c0 + 8);
            ql[ks][3] = *(const uint32_t*)(pl + 8 * EE + c0 + 8);
        }
    }

    float acc[8][4];
#pragma unroll
    for (int j = 0; j < 8; j++)
#pragma unroll
        for (int r = 0; r < 4; r++) acc[j][r] = 0.f;
    float m0 = -1e30f, m1 = -1e30f, l0 = 0.f, l1 = 0.f;

    const uint32_t fLane = (uint32_t)((lane & 7) + ((lane >> 4) & 1) * 8) * AROW
                         + ((lane >> 3) & 1) * 16;

    for (int kt = 0; kt < 16; kt++) {
        CP_WAIT(0);
        __syncthreads();
        if (kt < 15) issue(kt + 1, (kt + 1) & 1);

        const uint32_t sb = sbase + (kt & 1) * ABUF;
        const uint32_t kOff = sb + fLane;
        const uint32_t vOff = sb + 2 * ATILE + fLane;

        // ---- scores (Q pre-scaled by 1/8) ----
        float c[8][4];
#pragma unroll
        for (int j = 0; j < 8; j++)
#pragma unroll
            for (int r = 0; r < 4; r++) c[j][r] = 0.f;

#pragma unroll
        for (int ks = 0; ks < 4; ks++) {
#pragma unroll
            for (int p = 0; p < 4; p++) {
                uint32_t bh[4], bl[4];
                ldsm4(bh, kOff + p * 16 * AROW + ks * 32);
                ldsm4(bl, kOff + ATILE + p * 16 * AROW + ks * 32);
                mma_bf16(c[2 * p],     qh[ks], bh[0], bh[1]);
                mma_bf16(c[2 * p],     qh[ks], bl[0], bl[1]);
                mma_bf16(c[2 * p],     ql[ks], bh[0], bh[1]);
                mma_bf16(c[2 * p + 1], qh[ks], bh[2], bh[3]);
                mma_bf16(c[2 * p + 1], qh[ks], bl[2], bl[3]);
                mma_bf16(c[2 * p + 1], ql[ks], bh[2], bh[3]);
            }
        }

        // ---- online softmax in registers ----
        float mx0 = -1e30f, mx1 = -1e30f;
#pragma unroll
        for (int j = 0; j < 8; j++) {
            mx0 = fmaxf(mx0, fmaxf(c[j][0], c[j][1]));
            mx1 = fmaxf(mx1, fmaxf(c[j][2], c[j][3]));
        }
        mx0 = fmaxf(mx0, __shfl_xor_sync(0xffffffffu, mx0, 1));
        mx0 = fmaxf(mx0, __shfl_xor_sync(0xffffffffu, mx0, 2));
        mx1 = fmaxf(mx1, __shfl_xor_sync(0xffffffffu, mx1, 1));
        mx1 = fmaxf(mx1, __shfl_xor_sync(0xffffffffu, mx1, 2));
        float mn0 = fmaxf(m0, mx0), mn1 = fmaxf(m1, mx1);
        float cr0 = __expf(m0 - mn0), cr1 = __expf(m1 - mn1);
        float s0 = 0.f, s1 = 0.f;
#pragma unroll
        for (int j = 0; j < 8; j++) {
            c[j][0] = __expf(c[j][0] - mn0);
            c[j][1] = __expf(c[j][1] - mn0);
            c[j][2] = __expf(c[j][2] - mn1);
            c[j][3] = __expf(c[j][3] - mn1);
            s0 += c[j][0] + c[j][1];
            s1 += c[j][2] + c[j][3];
        }
        s0 += __shfl_xor_sync(0xffffffffu, s0, 1);
        s0 += __shfl_xor_sync(0xffffffffu, s0, 2);
        s1 += __shfl_xor_sync(0xffffffffu, s1, 1);
        s1 += __shfl_xor_sync(0xffffffffu, s1, 2);
        l0 = l0 * cr0 + s0;
        l1 = l1 * cr1 + s1;
        m0 = mn0; m1 = mn1;
#pragma unroll
        for (int j = 0; j < 8; j++) {
            acc[j][0] *= cr0; acc[j][1] *= cr0;
            acc[j][2] *= cr1; acc[j][3] *= cr1;
        }

        // ---- PV: P fragments packed in registers ----
#pragma unroll
        for (int ks = 0; ks < 4; ks++) {
            uint32_t ph[4], pl[4];
            split2(c[2 * ks][0],     c[2 * ks][1],     ph[0], pl[0]);
            split2(c[2 * ks][2],     c[2 * ks][3],     ph[1], pl[1]);
            split2(c[2 * ks + 1][0], c[2 * ks + 1][1], ph[2], pl[2]);
            split2(c[2 * ks + 1][2], c[2 * ks + 1][3], ph[3], pl[3]);
#pragma unroll
            for (int p = 0; p < 4; p++) {
                uint32_t vh[4], vl[4];
                ldsm4(vh, vOff + p * 16 * AROW + ks * 32);
                ldsm4(vl, vOff + ATILE + p * 16 * AROW + ks * 32);
                mma_bf16(acc[2 * p],     ph, vh[0], vh[1]);
                mma_bf16(acc[2 * p],     ph, vl[0], vl[1]);
                mma_bf16(acc[2 * p],     pl, vh[0], vh[1]);
                mma_bf16(acc[2 * p + 1], ph, vh[2], vh[3]);
                mma_bf16(acc[2 * p + 1], ph, vl[2], vl[3]);
                mma_bf16(acc[2 * p + 1], pl, vh[2], vh[3]);
            }
        }
    }

    // ---- epilogue: O = acc/l, write bf16 hi/lo ----
    float i0 = 1.f / l0, i1 = 1.f / l1;
    size_t rg = (size_t)(b * SS + qt * 128 + wid * 16 + g);
#pragma unroll
    for (int j = 0; j < 8; j++) {
        int col = h * 64 + j * 8 + 2 * tig;
        uint32_t hh, ll;
        split2(acc[j][0] * i0, acc[j][1] * i0, hh, ll);
        *(uint32_t*)(g_Oh + rg * EE + col) = hh;
        *(uint32_t*)(g_Ol + rg * EE + col) = ll;
        split2(acc[j][2] * i1, acc[j][3] * i1, hh, ll);
        *(uint32_t*)(g_Oh + (rg + 8) * EE + col) = hh;
        *(uint32_t*)(g_Ol + (rg + 8) * EE + col) = ll;
    }
}

// ---------------- LayerNorm ----------------
__global__ __launch_bounds__(256) void ln_kernel(
    const float* __restrict__ gamma, const float* __restrict__ beta,
    float* __restrict__ out)
{
    const int row = blockIdx.x;
    const int tid = threadIdx.x;
    const float4 v = *(const float4*)(g_R + (size_t)row * EE + tid * 4);

    float s1 = v.x + v.y + v.z + v.w;
    float s2 = v.x * v.x + v.y * v.y + v.z * v.z + v.w * v.w;

    __shared__ float sh1[8], sh2[8];
#pragma unroll
    for (int off = 16; off > 0; off >>= 1) {
        s1 += __shfl_xor_sync(0xffffffffu, s1, off);
        s2 += __shfl_xor_sync(0xffffffffu, s2, off);
    }
    const int warp = tid >> 5;
    if ((tid & 31) == 0) { sh1[warp] = s1; sh2[warp] = s2; }
    __syncthreads();
    float t1 = 0.f, t2 = 0.f;
#pragma unroll
    for (int w = 0; w < 8; w++) { t1 += sh1[w]; t2 += sh2[w]; }

    const float mean = t1 * (1.0f / EE);
    const float var  = t2 * (1.0f / EE) - mean * mean;
    const float inv  = rsqrtf(var + 1e-6f);

    const float4 gmv = *(const float4*)(gamma + tid * 4);
    const float4 btv = *(const float4*)(beta + tid * 4);
    float4 o;
    o.x = (v.x - mean) * inv * gmv.x + btv.x;
    o.y = (v.y - mean) * inv * gmv.y + btv.y;
    o.z = (v.z - mean) * inv * gmv.z + btv.z;
    o.w = (v.w - mean) * inv * gmv.w + btv.w;
    *(float4*)(out + (size_t)row * EE + tid * 4) = o;
}

// ---------------------------------------------------------------------------
extern "C" void kernel_launch(void* const* d_in, const int* in_sizes, int n_in,
                              void* d_out, int out_size)
{
    const float* X     = (const float*)d_in[0];
    const float* gQ    = (const float*)d_in[1];
    const float* gK    = (const float*)d_in[2];
    const float* Wq    = (const float*)d_in[3];
    const float* Wk    = (const float*)d_in[4];
    const float* Wv    = (const float*)d_in[5];
    const float* Wo    = (const float*)d_in[6];
    const float* gamma = (const float*)d_in[7];
    const float* beta  = (const float*)d_in[8];
    float* out = (float*)d_out;

    cudaFuncSetAttribute(gemm_kernel,
                         cudaFuncAttributeMaxDynamicSharedMemorySize, GEMM_SMEM);
    cudaFuncSetAttribute(attn_kernel,
                         cudaFuncAttributeMaxDynamicSharedMemorySize, ATTN_SMEM);

    prep_x_kernel<<<NELEM / 1024, 256>>>(X);
    prep_w_kernel<<<dim3(32, 32, 4), dim3(32, 8)>>>(Wq, Wk, Wv, Wo);

    gemm_kernel<<<dim3(8, 64, 3), 256, GEMM_SMEM>>>(gQ, gK, X, 0);

    attn_kernel<<<dim3(8, HH, BB), 256, ATTN_SMEM>>>();

    gemm_kernel<<<dim3(8, 64, 1), 256, GEMM_SMEM>>>(gQ, gK, X, 3);
    ln_kernel<<<M_TOT, 256>>>(gamma, beta, out);
}

// round 6
// speedup vs baseline: 2.4817x; 1.0083x over previous
#include <cuda_runtime.h>
#include <cuda_bf16.h>
#include <stdint.h>

#define BB 8
#define SS 1024
#define EE 1024
#define HH 16
#define M_TOT 8192
#define NELEM ((size_t)M_TOT * EE)   /* 8388608 */

// ---------------- scratch (device globals; no allocations) ----------------
__device__ __nv_bfloat16 g_Xh[NELEM], g_Xl[NELEM];
__device__ __nv_bfloat16 g_Wth[4 * 1048576], g_Wtl[4 * 1048576];  // [N][K] K-major
__device__ __nv_bfloat16 g_Qh[NELEM], g_Ql[NELEM];   // gate*2*0.125*log2e folded
__device__ __nv_bfloat16 g_Kh[NELEM], g_Kl[NELEM];   // gate*2 folded
__device__ __nv_bfloat16 g_Vth[NELEM], g_Vtl[NELEM]; // [(b*H+h)*64+d][s]
__device__ __nv_bfloat16 g_Oh[NELEM], g_Ol[NELEM];
__device__ float g_R[NELEM];

// ---------------- helpers ----------------
__device__ __forceinline__ void mma_bf16(float* c, const uint32_t* a,
                                         uint32_t b0, uint32_t b1) {
    asm volatile(
        "mma.sync.aligned.m16n8k16.row.col.f32.bf16.bf16.f32 "
        "{%0,%1,%2,%3}, {%4,%5,%6,%7}, {%8,%9}, {%0,%1,%2,%3};"
        : "+f"(c[0]), "+f"(c[1]), "+f"(c[2]), "+f"(c[3])
        : "r"(a[0]), "r"(a[1]), "r"(a[2]), "r"(a[3]), "r"(b0), "r"(b1));
}

__device__ __forceinline__ void ldsm4(uint32_t* r, uint32_t addr) {
    asm volatile("ldmatrix.sync.aligned.m8n8.x4.shared.b16 {%0,%1,%2,%3}, [%4];"
                 : "=r"(r[0]), "=r"(r[1]), "=r"(r[2]), "=r"(r[3]) : "r"(addr));
}

__device__ __forceinline__ void cp16(uint32_t s, const void* g) {
    asm volatile("cp.async.cg.shared.global [%0], [%1], 16;" :: "r"(s), "l"(g));
}
#define CP_COMMIT asm volatile("cp.async.commit_group;" ::: "memory")
#define CP_WAIT(n) asm volatile("cp.async.wait_group %0;" :: "n"(n) : "memory")

__device__ __forceinline__ uint32_t smem_u32(const void* p) {
    uint32_t a;
    asm("{ .reg .u64 t; cvta.to.shared.u64 t, %1; cvt.u32.u64 %0, t; }"
        : "=r"(a) : "l"(p));
    return a;
}

__device__ __forceinline__ void split2(float x, float y, uint32_t& h, uint32_t& l) {
    __nv_bfloat162 hh = __floats2bfloat162_rn(x, y);
    __nv_bfloat162 ll = __floats2bfloat162_rn(x - __bfloat162float(hh.x),
                                              y - __bfloat162float(hh.y));
    h = *(uint32_t*)&hh;
    l = *(uint32_t*)&ll;
}

__device__ __forceinline__ void split1(float x, __nv_bfloat16& h, __nv_bfloat16& l) {
    h = __float2bfloat16(x);
    l = __float2bfloat16(x - __bfloat162float(h));
}

// ---------------- prep: split X ----------------
__global__ __launch_bounds__(256) void prep_x_kernel(const float* __restrict__ X)
{
    size_t i = ((size_t)blockIdx.x * 256 + threadIdx.x) * 4;
    float4 v = *(const float4*)(X + i);
    uint32_t h01, l01, h23, l23;
    split2(v.x, v.y, h01, l01);
    split2(v.z, v.w, h23, l23);
    *(uint32_t*)(g_Xh + i)     = h01;
    *(uint32_t*)(g_Xh + i + 2) = h23;
    *(uint32_t*)(g_Xl + i)     = l01;
    *(uint32_t*)(g_Xl + i + 2) = l23;
}

// ---------------- prep: weights -> K-major bf16 hi/lo ----------------
__global__ __launch_bounds__(256) void prep_w_kernel(
    const float* __restrict__ Wq, const float* __restrict__ Wk,
    const float* __restrict__ Wv, const float* __restrict__ Wo)
{
    const int which = blockIdx.z;
    const float* W = (which == 0) ? Wq : (which == 1) ? Wk : (which == 2) ? Wv : Wo;
    __nv_bfloat16* Oh = g_Wth + (size_t)which * 1048576;
    __nv_bfloat16* Ol = g_Wtl + (size_t)which * 1048576;

    __shared__ float tile[32][33];
    const int tx = threadIdx.x, ty = threadIdx.y;
    const int n0 = blockIdx.x * 32, k0 = blockIdx.y * 32;

    if (which < 3) {
#pragma unroll
        for (int i = 0; i < 4; i++)
            tile[ty + 8 * i][tx] = W[(size_t)(k0 + ty + 8 * i) * EE + n0 + tx];
        __syncthreads();
#pragma unroll
        for (int i = 0; i < 4; i++) {
            float v = tile[tx][ty + 8 * i];
            __nv_bfloat16 h, l;
            split1(v, h, l);
            size_t o = (size_t)(n0 + ty + 8 * i) * EE + k0 + tx;
            Oh[o] = h; Ol[o] = l;
        }
    } else {
#pragma unroll
        for (int i = 0; i < 4; i++) {
            size_t o = (size_t)(n0 + ty + 8 * i) * EE + k0 + tx;
            float v = W[o];
            __nv_bfloat16 h, l;
            split1(v, h, l);
            Oh[o] = h; Ol[o] = l;
        }
    }
}

// ---------------- GEMM: cp.async 3-stage + ldmatrix + term-major MMA ----------
#define GROW 80                            /* 64B data + 16 pad */
#define GTILE (128 * GROW)                 /* 10240 */
#define GSTAGE (4 * GTILE)                 /* Ah, Al, Bh, Bl = 40960 */
#define GEMM_SMEM (3 * GSTAGE)             /* 122880 */

__global__ __launch_bounds__(256, 1) void gemm_kernel(
    const float* __restrict__ AuxQ, const float* __restrict__ AuxK,
    const float* __restrict__ AuxX, int modeBase)
{
    extern __shared__ char smb[];
    const uint32_t sbase = smem_u32(smb);

    const int mode = modeBase + blockIdx.z;
    const __nv_bfloat16* Ah = (mode == 3) ? g_Oh : g_Xh;
    const __nv_bfloat16* Al = (mode == 3) ? g_Ol : g_Xl;
    const __nv_bfloat16* Bhp = g_Wth + (size_t)mode * 1048576;
    const __nv_bfloat16* Blp = g_Wtl + (size_t)mode * 1048576;

    const int tid = threadIdx.x;
    const int wid = tid >> 5;
    const int lane = tid & 31;
    const int g = lane >> 2;
    const int tig = lane & 3;
    const int wm = wid >> 1;
    const int wn = wid & 1;
    const int colBase = blockIdx.x * 128;
    const int rowBase = blockIdx.y * 128;

    float c[2][8][4];
#pragma unroll
    for (int mt = 0; mt < 2; mt++)
#pragma unroll
        for (int nt = 0; nt < 8; nt++)
#pragma unroll
            for (int r = 0; r < 4; r++) c[mt][nt][r] = 0.f;

    const uint32_t aLane = (uint32_t)(wm * 32 + (lane & 7) + ((lane >> 3) & 1) * 8) * GROW
                         + ((lane >> 4) & 1) * 16;
    const uint32_t bLane = (uint32_t)(wn * 64 + (lane & 7) + ((lane >> 4) & 1) * 8) * GROW
                         + ((lane >> 3) & 1) * 16;

    auto issue = [&](int kt, int stage) {
        uint32_t sb = sbase + stage * GSTAGE;
#pragma unroll
        for (int i = 0; i < 2; i++) {
            int ch = tid * 2 + i;
            int r = ch >> 2;
            int cb = (ch & 3) * 16;
            size_t ao = (size_t)(rowBase + r) * EE + kt * 32 + (ch & 3) * 8;
            size_t bo = (size_t)(colBase + r) * EE + kt * 32 + (ch & 3) * 8;
            uint32_t off = r * GROW + cb;
            cp16(sb + off,             Ah + ao);
            cp16(sb + GTILE + off,     Al + ao);
            cp16(sb + 2 * GTILE + off, Bhp + bo);
            cp16(sb + 3 * GTILE + off, Blp + bo);
        }
        CP_COMMIT;
    };

    issue(0, 0);
    issue(1, 1);

    for (int kt = 0; kt < 32; kt++) {
        if (kt < 31) { CP_WAIT(1); } else { CP_WAIT(0); }
        __syncthreads();
        if (kt + 2 < 32) issue(kt + 2, (kt + 2) % 3);

        const uint32_t sb = sbase + (kt % 3) * GSTAGE;
        const uint32_t aOff = sb + aLane;
        const uint32_t bOff = sb + 2 * GTILE + bLane;

#pragma unroll
        for (int ks = 0; ks < 2; ks++) {
            uint32_t ah[2][4], al[2][4];
            ldsm4(ah[0], aOff + ks * 32);
            ldsm4(ah[1], aOff + 16 * GROW + ks * 32);
            ldsm4(al[0], aOff + GTILE + ks * 32);
            ldsm4(al[1], aOff + GTILE + 16 * GROW + ks * 32);
            uint32_t bh[4][4], bl[4][4];
#pragma unroll
            for (int p = 0; p < 4; p++) {
                ldsm4(bh[p], bOff + p * 16 * GROW + ks * 32);
                ldsm4(bl[p], bOff + GTILE + p * 16 * GROW + ks * 32);
            }
            // pass 1: Ah*Bh — 16 independent MMAs
#pragma unroll
            for (int p = 0; p < 4; p++)
#pragma unroll
                for (int mt = 0; mt < 2; mt++) {
                    mma_bf16(c[mt][2 * p],     ah[mt], bh[p][0], bh[p][1]);
                    mma_bf16(c[mt][2 * p + 1], ah[mt], bh[p][2], bh[p][3]);
                }
            // pass 2: Ah*Bl
#pragma unroll
            for (int p = 0; p < 4; p++)
#pragma unroll
                for (int mt = 0; mt < 2; mt++) {
                    mma_bf16(c[mt][2 * p],     ah[mt], bl[p][0], bl[p][1]);
                    mma_bf16(c[mt][2 * p + 1], ah[mt], bl[p][2], bl[p][3]);
                }
            // pass 3: Al*Bh
#pragma unroll
            for (int p = 0; p < 4; p++)
#pragma unroll
                for (int mt = 0; mt < 2; mt++) {
                    mma_bf16(c[mt][2 * p],     al[mt], bh[p][0], bh[p][1]);
                    mma_bf16(c[mt][2 * p + 1], al[mt], bh[p][2], bh[p][3]);
                }
        }
    }

    // ---- epilogues ----
    const int batch = rowBase / SS;
    if (mode <= 1) {
        __nv_bfloat16* Oh = (mode == 0) ? g_Qh : g_Kh;
        __nv_bfloat16* Ol = (mode == 0) ? g_Ql : g_Kl;
        // Q: gate*2*0.125*log2e ; K: gate*2
        const float sc = (mode == 0) ? 0.25f * 1.44269504089f : 2.0f;
        const float* Aux = (mode == 0) ? AuxQ : AuxK;
#pragma unroll
        for (int mt = 0; mt < 2; mt++) {
            size_t row0 = (size_t)rowBase + wm * 32 + mt * 16 + g;
#pragma unroll
            for (int nt = 0; nt < 8; nt++) {
                int col = colBase + wn * 64 + nt * 8 + 2 * tig;
                float2 gv = *(const float2*)(Aux + (size_t)batch * EE + col);
                float gx = gv.x * sc, gy = gv.y * sc;
                uint32_t h, l;
                split2(c[mt][nt][0] * gx, c[mt][nt][1] * gy, h, l);
                *(uint32_t*)(Oh + row0 * EE + col) = h;
                *(uint32_t*)(Ol + row0 * EE + col) = l;
                split2(c[mt][nt][2] * gx, c[mt][nt][3] * gy, h, l);
                *(uint32_t*)(Oh + (row0 + 8) * EE + col) = h;
                *(uint32_t*)(Ol + (row0 + 8) * EE + col) = l;
            }
        }
    } else if (mode == 2) {
#pragma unroll
        for (int mt = 0; mt < 2; mt++) {
            int row0 = rowBase + wm * 32 + mt * 16 + g;
            int s = row0 - batch * SS;
#pragma unroll
            for (int nt = 0; nt < 8; nt++) {
                int col = colBase + wn * 64 + nt * 8 + 2 * tig;
                int hh = col >> 6, d = col & 63;
                size_t vb = ((size_t)(batch * HH + hh) * 64 + d) * SS + s;
                __nv_bfloat16 h, l;
                split1(c[mt][nt][0], h, l); g_Vth[vb] = h;          g_Vtl[vb] = l;
                split1(c[mt][nt][1], h, l); g_Vth[vb + SS] = h;     g_Vtl[vb + SS] = l;
                split1(c[mt][nt][2], h, l); g_Vth[vb + 8] = h;      g_Vtl[vb + 8] = l;
                split1(c[mt][nt][3], h, l); g_Vth[vb + SS + 8] = h; g_Vtl[vb + SS + 8] = l;
            }
        }
    } else {
#pragma unroll
        for (int mt = 0; mt < 2; mt++) {
            size_t row0 = (size_t)rowBase + wm * 32 + mt * 16 + g;
#pragma unroll
            for (int nt = 0; nt < 8; nt++) {
                int col = colBase + wn * 64 + nt * 8 + 2 * tig;
                float2 x0 = *(const float2*)(AuxX + row0 * EE + col);
                float2 x1 = *(const float2*)(AuxX + (row0 + 8) * EE + col);
                *(float2*)(g_R + row0 * EE + col) =
                    make_float2(c[mt][nt][0] + x0.x, c[mt][nt][1] + x0.y);
                *(float2*)(g_R + (row0 + 8) * EE + col) =
                    make_float2(c[mt][nt][2] + x1.x, c[mt][nt][3] + x1.y);
            }
        }
    }
}

// ---------------- tensor-core flash attention (term-major + exp2) ----------
#define AROW 144
#define ATILE (64 * AROW)
#define ABUF (4 * ATILE)
#define ATTN_SMEM (2 * ABUF)

__global__ __launch_bounds__(256, 1) void attn_kernel()
{
    extern __shared__ char smb[];
    const uint32_t sbase = smem_u32(smb);

    const int qt = blockIdx.x;
    const int h  = blockIdx.y;
    const int b  = blockIdx.z;
    const int tid = threadIdx.x;
    const int wid = tid >> 5;
    const int lane = tid & 31;
    const int g = lane >> 2;
    const int tig = lane & 3;

    const size_t kbase0 = ((size_t)b * SS) * EE + h * 64;
    const size_t vbase0 = ((size_t)(b * HH + h) * 64) * SS;

    auto issue = [&](int kt, int stage) {
        uint32_t sb = sbase + stage * ABUF;
#pragma unroll
        for (int i = 0; i < 2; i++) {
            int ch = tid * 2 + i;
            int r = ch >> 3;
            int cb = (ch & 7) * 16;
            int c8 = (ch & 7) * 8;
            size_t ko = kbase0 + (size_t)(kt * 64 + r) * EE + c8;
            size_t vo = vbase0 + (size_t)r * SS + kt * 64 + c8;
            uint32_t off = r * AROW + cb;
            cp16(sb + off,             g_Kh + ko);
            cp16(sb + ATILE + off,     g_Kl + ko);
            cp16(sb + 2 * ATILE + off, g_Vth + vo);
            cp16(sb + 3 * ATILE + off, g_Vtl + vo);
        }
        CP_COMMIT;
    };

    issue(0, 0);

    // ---- Q fragments (held all kernel; log2e pre-folded) ----
    uint32_t qh[4][4], ql[4][4];
    {
        size_t rg = (size_t)(b * SS + qt * 128 + wid * 16 + g);
        const __nv_bfloat16* ph = g_Qh + rg * EE + h * 64;
        const __nv_bfloat16* pl = g_Ql + rg * EE + h * 64;
#pragma unroll
        for (int ks = 0; ks < 4; ks++) {
            int c0 = ks * 16 + 2 * tig;
            qh[ks][0] = *(const uint32_t*)(ph + c0);
            qh[ks][1] = *(const uint32_t*)(ph + 8 * EE + c0);
            qh[ks][2] = *(const uint32_t*)(ph + c0 + 8);
            qh[ks][3] = *(const uint32_t*)(ph + 8 * EE + c0 + 8);
            ql[ks][0] = *(const uint32_t*)(pl + c0);
            ql[ks][1] = *(const uint32_t*)(pl + 8 * EE + c0);
            ql[ks][2] = *(const uint32_t*)(pl + c0 + 8);
            ql[ks][3] = *(const uint32_t*)(pl + 8 * EE + c0 + 8);
        }
    }

    float acc[8][4];
#pragma unroll
    for (int j = 0; j < 8; j++)
#pragma unroll
        for (int r = 0; r < 4; r++) acc[j][r] = 0.f;
    float m0 = -1e30f, m1 = -1e30f, l0 = 0.f, l1 = 0.f;

    const uint32_t fLane = (uint32_t)((lane & 7) + ((lane >> 4) & 1) * 8) * AROW
                         + ((lane >> 3) & 1) * 16;

    for (int kt = 0; kt < 16; kt++) {
        CP_WAIT(0);
        __syncthreads();
        if (kt < 15) issue(kt + 1, (kt + 1) & 1);

        const uint32_t sb = sbase + (kt & 1) * ABUF;
        const uint32_t kOff = sb + fLane;
        const uint32_t vOff = sb + 2 * ATILE + fLane;

        // ---- scores (log2 domain) ----
        float c[8][4];
#pragma unroll
        for (int j = 0; j < 8; j++)
#pragma unroll
            for (int r = 0; r < 4; r++) c[j][r] = 0.f;

#pragma unroll
        for (int ks = 0; ks < 4; ks++) {
            uint32_t bh[4][4], bl[4][4];
#pragma unroll
            for (int p = 0; p < 4; p++) {
                ldsm4(bh[p], kOff + p * 16 * AROW + ks * 32);
                ldsm4(bl[p], kOff + ATILE + p * 16 * AROW + ks * 32);
            }
#pragma unroll
            for (int p = 0; p < 4; p++) {
                mma_bf16(c[2 * p],     qh[ks], bh[p][0], bh[p][1]);
                mma_bf16(c[2 * p + 1], qh[ks], bh[p][2], bh[p][3]);
            }
#pragma unroll
            for (int p = 0; p < 4; p++) {
                mma_bf16(c[2 * p],     qh[ks], bl[p][0], bl[p][1]);
                mma_bf16(c[2 * p + 1], qh[ks], bl[p][2], bl[p][3]);
            }
#pragma unroll
            for (int p = 0; p < 4; p++) {
                mma_bf16(c[2 * p],     ql[ks], bh[p][0], bh[p][1]);
                mma_bf16(c[2 * p + 1], ql[ks], bh[p][2], bh[p][3]);
            }
        }

        // ---- online softmax (exp2 domain) ----
        float mx0 = -1e30f, mx1 = -1e30f;
#pragma unroll
        for (int j = 0; j < 8; j++) {
            mx0 = fmaxf(mx0, fmaxf(c[j][0], c[j][1]));
            mx1 = fmaxf(mx1, fmaxf(c[j][2], c[j][3]));
        }
        mx0 = fmaxf(mx0, __shfl_xor_sync(0xffffffffu, mx0, 1));
        mx0 = fmaxf(mx0, __shfl_xor_sync(0xffffffffu, mx0, 2));
        mx1 = fmaxf(mx1, __shfl_xor_sync(0xffffffffu, mx1, 1));
        mx1 = fmaxf(mx1, __shfl_xor_sync(0xffffffffu, mx1, 2));
        float mn0 = fmaxf(m0, mx0), mn1 = fmaxf(m1, mx1);
        float cr0 = exp2f(m0 - mn0), cr1 = exp2f(m1 - mn1);
        float s0 = 0.f, s1 = 0.f;
#pragma unroll
        for (int j = 0; j < 8; j++) {
            c[j][0] = exp2f(c[j][0] - mn0);
            c[j][1] = exp2f(c[j][1] - mn0);
            c[j][2] = exp2f(c[j][2] - mn1);
            c[j][3] = exp2f(c[j][3] - mn1);
            s0 += c[j][0] + c[j][1];
            s1 += c[j][2] + c[j][3];
        }
        s0 += __shfl_xor_sync(0xffffffffu, s0, 1);
        s0 += __shfl_xor_sync(0xffffffffu, s0, 2);
        s1 += __shfl_xor_sync(0xffffffffu, s1, 1);
        s1 += __shfl_xor_sync(0xffffffffu, s1, 2);
        l0 = l0 * cr0 + s0;
        l1 = l1 * cr1 + s1;
        m0 = mn0; m1 = mn1;
#pragma unroll
        for (int j = 0; j < 8; j++) {
            acc[j][0] *= cr0; acc[j][1] *= cr0;
            acc[j][2] *= cr1; acc[j][3] *= cr1;
        }

        // ---- PV: term-major within each ks ----
#pragma unroll
        for (int ks = 0; ks < 4; ks++) {
            uint32_t ph[4], pl[4];
            split2(c[2 * ks][0],     c[2 * ks][1],     ph[0], pl[0]);
            split2(c[2 * ks][2],     c[2 * ks][3],     ph[1], pl[1]);
            split2(c[2 * ks + 1][0], c[2 * ks + 1][1], ph[2], pl[2]);
            split2(c[2 * ks + 1][2], c[2 * ks + 1][3], ph[3], pl[3]);
            uint32_t vh[4][4], vl[4][4];
#pragma unroll
            for (int p = 0; p < 4; p++) {
                ldsm4(vh[p], vOff + p * 16 * AROW + ks * 32);
                ldsm4(vl[p], vOff + ATILE + p * 16 * AROW + ks * 32);
            }
#pragma unroll
            for (int p = 0; p < 4; p++) {
                mma_bf16(acc[2 * p],     ph, vh[p][0], vh[p][1]);
                mma_bf16(acc[2 * p + 1], ph, vh[p][2], vh[p][3]);
            }
#pragma unroll
            for (int p = 0; p < 4; p++) {
                mma_bf16(acc[2 * p],     ph, vl[p][0], vl[p][1]);
                mma_bf16(acc[2 * p + 1], ph, vl[p][2], vl[p][3]);
            }
#pragma unroll
            for (int p = 0; p < 4; p++) {
                mma_bf16(acc[2 * p],     pl, vh[p][0], vh[p][1]);
                mma_bf16(acc[2 * p + 1], pl, vh[p][2], vh[p][3]);
            }
        }
    }

    // ---- epilogue ----
    float i0 = 1.f / l0, i1 = 1.f / l1;
    size_t rg = (size_t)(b * SS + qt * 128 + wid * 16 + g);
#pragma unroll
    for (int j = 0; j < 8; j++) {
        int col = h * 64 + j * 8 + 2 * tig;
        uint32_t hh, ll;
        split2(acc[j][0] * i0, acc[j][1] * i0, hh, ll);
        *(uint32_t*)(g_Oh + rg * EE + col) = hh;
        *(uint32_t*)(g_Ol + rg * EE + col) = ll;
        split2(acc[j][2] * i1, acc[j][3] * i1, hh, ll);
        *(uint32_t*)(g_Oh + (rg + 8) * EE + col) = hh;
        *(uint32_t*)(g_Ol + (rg + 8) * EE + col) = ll;
    }
}

// ---------------- LayerNorm ----------------
__global__ __launch_bounds__(256) void ln_kernel(
    const float* __restrict__ gamma, const float* __restrict__ beta,
    float* __restrict__ out)
{
    const int row = blockIdx.x;
    const int tid = threadIdx.x;
    const float4 v = *(const float4*)(g_R + (size_t)row * EE + tid * 4);

    float s1 = v.x + v.y + v.z + v.w;
    float s2 = v.x * v.x + v.y * v.y + v.z * v.z + v.w * v.w;

    __shared__ float sh1[8], sh2[8];
#pragma unroll
    for (int off = 16; off > 0; off >>= 1) {
        s1 += __shfl_xor_sync(0xffffffffu, s1, off);
        s2 += __shfl_xor_sync(0xffffffffu, s2, off);
    }
    const int warp = tid >> 5;
    if ((tid & 31) == 0) { sh1[warp] = s1; sh2[warp] = s2; }
    __syncthreads();
    float t1 = 0.f, t2 = 0.f;
#pragma unroll
    for (int w = 0; w < 8; w++) { t1 += sh1[w]; t2 += sh2[w]; }

    const float mean = t1 * (1.0f / EE);
    const float var  = t2 * (1.0f / EE) - mean * mean;
    const float inv  = rsqrtf(var + 1e-6f);

    const float4 gmv = *(const float4*)(gamma + tid * 4);
    const float4 btv = *(const float4*)(beta + tid * 4);
    float4 o;
    o.x = (v.x - mean) * inv * gmv.x + btv.x;
    o.y = (v.y - mean) * inv * gmv.y + btv.y;
    o.z = (v.z - mean) * inv * gmv.z + btv.z;
    o.w = (v.w - mean) * inv * gmv.w + btv.w;
    *(float4*)(out + (size_t)row * EE + tid * 4) = o;
}

// ---------------------------------------------------------------------------
extern "C" void kernel_launch(void* const* d_in, const int* in_sizes, int n_in,
                              void* d_out, int out_size)
{
    const float* X     = (const float*)d_in[0];
    const float* gQ    = (const float*)d_in[1];
    const float* gK    = (const float*)d_in[2];
    const float* Wq    = (const float*)d_in[3];
    const float* Wk    = (const float*)d_in[4];
    const float* Wv    = (const float*)d_in[5];
    const float* Wo    = (const float*)d_in[6];
    const float* gamma = (const float*)d_in[7];
    const float* beta  = (const float*)d_in[8];
    float* out = (float*)d_out;

    cudaFuncSetAttribute(gemm_kernel,
                         cudaFuncAttributeMaxDynamicSharedMemorySize, GEMM_SMEM);
    cudaFuncSetAttribute(attn_kernel,
                         cudaFuncAttributeMaxDynamicSharedMemorySize, ATTN_SMEM);

    prep_x_kernel<<<NELEM / 1024, 256>>>(X);
    prep_w_kernel<<<dim3(32, 32, 4), dim3(32, 8)>>>(Wq, Wk, Wv, Wo);

    gemm_kernel<<<dim3(8, 64, 3), 256, GEMM_SMEM>>>(gQ, gK, X, 0);

    attn_kernel<<<dim3(8, HH, BB), 256, ATTN_SMEM>>>();

    gemm_kernel<<<dim3(8, 64, 1), 256, GEMM_SMEM>>>(gQ, gK, X, 3);
    ln_kernel<<<M_TOT, 256>>>(gamma, beta, out);
}

// round 7
// speedup vs baseline: 2.9509x; 1.1890x over previous
#include <cuda_runtime.h>
#include <cuda_bf16.h>
#include <stdint.h>

#define BB 8
#define SS 1024
#define EE 1024
#define HH 16
#define M_TOT 8192
#define NELEM ((size_t)M_TOT * EE)   /* 8388608 */

// ---------------- scratch (device globals; no allocations) ----------------
__device__ __nv_bfloat16 g_Xh[NELEM], g_Xl[NELEM];
__device__ __nv_bfloat16 g_Wth[4 * 1048576], g_Wtl[4 * 1048576];  // [N][K] K-major
__device__ __nv_bfloat16 g_Qh[NELEM], g_Ql[NELEM];   // gate*2*0.125*log2e folded
__device__ __nv_bfloat16 g_Kh[NELEM], g_Kl[NELEM];   // gate*2 folded
__device__ __nv_bfloat16 g_Vth[NELEM], g_Vtl[NELEM]; // [(b*H+h)*64+d][s]
__device__ __nv_bfloat16 g_Oh[NELEM], g_Ol[NELEM];
__device__ float g_R[NELEM];

// ---------------- helpers ----------------
__device__ __forceinline__ void mma_bf16(float* c, const uint32_t* a,
                                         uint32_t b0, uint32_t b1) {
    asm volatile(
        "mma.sync.aligned.m16n8k16.row.col.f32.bf16.bf16.f32 "
        "{%0,%1,%2,%3}, {%4,%5,%6,%7}, {%8,%9}, {%0,%1,%2,%3};"
        : "+f"(c[0]), "+f"(c[1]), "+f"(c[2]), "+f"(c[3])
        : "r"(a[0]), "r"(a[1]), "r"(a[2]), "r"(a[3]), "r"(b0), "r"(b1));
}

__device__ __forceinline__ void ldsm4(uint32_t* r, uint32_t addr) {
    asm volatile("ldmatrix.sync.aligned.m8n8.x4.shared.b16 {%0,%1,%2,%3}, [%4];"
                 : "=r"(r[0]), "=r"(r[1]), "=r"(r[2]), "=r"(r[3]) : "r"(addr));
}

__device__ __forceinline__ void cp16(uint32_t s, const void* g) {
    asm volatile("cp.async.cg.shared.global [%0], [%1], 16;" :: "r"(s), "l"(g));
}
#define CP_COMMIT asm volatile("cp.async.commit_group;" ::: "memory")
#define CP_WAIT(n) asm volatile("cp.async.wait_group %0;" :: "n"(n) : "memory")

__device__ __forceinline__ uint32_t smem_u32(const void* p) {
    uint32_t a;
    asm("{ .reg .u64 t; cvta.to.shared.u64 t, %1; cvt.u32.u64 %0, t; }"
        : "=r"(a) : "l"(p));
    return a;
}

__device__ __forceinline__ void split2(float x, float y, uint32_t& h, uint32_t& l) {
    __nv_bfloat162 hh = __floats2bfloat162_rn(x, y);
    __nv_bfloat162 ll = __floats2bfloat162_rn(x - __bfloat162float(hh.x),
                                              y - __bfloat162float(hh.y));
    h = *(uint32_t*)&hh;
    l = *(uint32_t*)&ll;
}

__device__ __forceinline__ void split1(float x, __nv_bfloat16& h, __nv_bfloat16& l) {
    h = __float2bfloat16(x);
    l = __float2bfloat16(x - __bfloat162float(h));
}

// ---------------- prep: split X ----------------
__global__ __launch_bounds__(256) void prep_x_kernel(const float* __restrict__ X)
{
    size_t i = ((size_t)blockIdx.x * 256 + threadIdx.x) * 4;
    float4 v = *(const float4*)(X + i);
    uint32_t h01, l01, h23, l23;
    split2(v.x, v.y, h01, l01);
    split2(v.z, v.w, h23, l23);
    *(uint32_t*)(g_Xh + i)     = h01;
    *(uint32_t*)(g_Xh + i + 2) = h23;
    *(uint32_t*)(g_Xl + i)     = l01;
    *(uint32_t*)(g_Xl + i + 2) = l23;
}

// ---------------- prep: weights -> K-major bf16 hi/lo ----------------
__global__ __launch_bounds__(256) void prep_w_kernel(
    const float* __restrict__ Wq, const float* __restrict__ Wk,
    const float* __restrict__ Wv, const float* __restrict__ Wo)
{
    const int which = blockIdx.z;
    const float* W = (which == 0) ? Wq : (which == 1) ? Wk : (which == 2) ? Wv : Wo;
    __nv_bfloat16* Oh = g_Wth + (size_t)which * 1048576;
    __nv_bfloat16* Ol = g_Wtl + (size_t)which * 1048576;

    __shared__ float tile[32][33];
    const int tx = threadIdx.x, ty = threadIdx.y;
    const int n0 = blockIdx.x * 32, k0 = blockIdx.y * 32;

    if (which < 3) {
#pragma unroll
        for (int i = 0; i < 4; i++)
            tile[ty + 8 * i][tx] = W[(size_t)(k0 + ty + 8 * i) * EE + n0 + tx];
        __syncthreads();
#pragma unroll
        for (int i = 0; i < 4; i++) {
            float v = tile[tx][ty + 8 * i];
            __nv_bfloat16 h, l;
            split1(v, h, l);
            size_t o = (size_t)(n0 + ty + 8 * i) * EE + k0 + tx;
            Oh[o] = h; Ol[o] = l;
        }
    } else {
#pragma unroll
        for (int i = 0; i < 4; i++) {
            size_t o = (size_t)(n0 + ty + 8 * i) * EE + k0 + tx;
            float v = W[o];
            __nv_bfloat16 h, l;
            split1(v, h, l);
            Oh[o] = h; Ol[o] = l;
        }
    }
}

// ---------------- GEMM: 128 threads, tile 128x64, 2 CTAs/SM ----------------
#define GROW 80                            /* 64B data + 16 pad */
#define GTA (128 * GROW)                   /* A tile 10240 */
#define GTB (64 * GROW)                    /* B tile 5120 */
#define GSTAGE (2 * GTA + 2 * GTB)         /* Ah, Al, Bh, Bl = 30720 */
#define GEMM_SMEM (3 * GSTAGE)             /* 92160 */

__global__ __launch_bounds__(128, 2) void gemm_kernel(
    const float* __restrict__ AuxQ, const float* __restrict__ AuxK,
    const float* __restrict__ AuxX, int modeBase)
{
    extern __shared__ char smb[];
    const uint32_t sbase = smem_u32(smb);

    const int mode = modeBase + blockIdx.z;
    const __nv_bfloat16* Ahp = (mode == 3) ? g_Oh : g_Xh;
    const __nv_bfloat16* Alp = (mode == 3) ? g_Ol : g_Xl;
    const __nv_bfloat16* Bhp = g_Wth + (size_t)mode * 1048576;
    const __nv_bfloat16* Blp = g_Wtl + (size_t)mode * 1048576;

    const int tid = threadIdx.x;
    const int wid = tid >> 5;
    const int lane = tid & 31;
    const int g = lane >> 2;
    const int tig = lane & 3;
    const int wm = wid >> 1;       // 0..1 (64 rows each)
    const int wn = wid & 1;        // 0..1 (32 cols each)
    const int colBase = blockIdx.x * 64;
    const int rowBase = blockIdx.y * 128;

    float c[4][4][4];
#pragma unroll
    for (int mt = 0; mt < 4; mt++)
#pragma unroll
        for (int nt = 0; nt < 4; nt++)
#pragma unroll
            for (int r = 0; r < 4; r++) c[mt][nt][r] = 0.f;

    const uint32_t aLane = (uint32_t)(wm * 64 + (lane & 7) + ((lane >> 3) & 1) * 8) * GROW
                         + ((lane >> 4) & 1) * 16;
    const uint32_t bLane = (uint32_t)(wn * 32 + (lane & 7) + ((lane >> 4) & 1) * 8) * GROW
                         + ((lane >> 3) & 1) * 16;

    auto issue = [&](int kt, int stage) {
        uint32_t sb = sbase + stage * GSTAGE;
        // A: 128 rows x 4 chunks = 512, 128 threads -> 4 each (h and l)
#pragma unroll
        for (int i = 0; i < 4; i++) {
            int ch = tid + i * 128;
            int r = ch >> 2;
            int cb = (ch & 3) * 16;
            size_t ao = (size_t)(rowBase + r) * EE + kt * 32 + (ch & 3) * 8;
            uint32_t off = r * GROW + cb;
            cp16(sb + off,       Ahp + ao);
            cp16(sb + GTA + off, Alp + ao);
        }
        // B: 64 rows x 4 chunks = 256 -> 2 each
#pragma unroll
        for (int i = 0; i < 2; i++) {
            int ch = tid + i * 128;
            int r = ch >> 2;
            int cb = (ch & 3) * 16;
            size_t bo = (size_t)(colBase + r) * EE + kt * 32 + (ch & 3) * 8;
            uint32_t off = r * GROW + cb;
            cp16(sb + 2 * GTA + off,       Bhp + bo);
            cp16(sb + 2 * GTA + GTB + off, Blp + bo);
        }
        CP_COMMIT;
    };

    issue(0, 0);
    issue(1, 1);

    for (int kt = 0; kt < 32; kt++) {
        if (kt < 31) { CP_WAIT(1); } else { CP_WAIT(0); }
        __syncthreads();
        if (kt + 2 < 32) issue(kt + 2, (kt + 2) % 3);

        const uint32_t sb = sbase + (kt % 3) * GSTAGE;
        const uint32_t aOff = sb + aLane;
        const uint32_t bOff = sb + 2 * GTA + bLane;

#pragma unroll
        for (int ks = 0; ks < 2; ks++) {
            uint32_t ah[4][4], al[4][4];
#pragma unroll
            for (int mt = 0; mt < 4; mt++) {
                ldsm4(ah[mt], aOff + mt * 16 * GROW + ks * 32);
                ldsm4(al[mt], aOff + GTA + mt * 16 * GROW + ks * 32);
            }
            uint32_t bh[2][4], bl[2][4];
#pragma unroll
            for (int p = 0; p < 2; p++) {
                ldsm4(bh[p], bOff + p * 16 * GROW + ks * 32);
                ldsm4(bl[p], bOff + GTB + p * 16 * GROW + ks * 32);
            }
            // pass 1: Ah*Bh
#pragma unroll
            for (int p = 0; p < 2; p++)
#pragma unroll
                for (int mt = 0; mt < 4; mt++) {
                    mma_bf16(c[mt][2 * p],     ah[mt], bh[p][0], bh[p][1]);
                    mma_bf16(c[mt][2 * p + 1], ah[mt], bh[p][2], bh[p][3]);
                }
            // pass 2: Ah*Bl
#pragma unroll
            for (int p = 0; p < 2; p++)
#pragma unroll
                for (int mt = 0; mt < 4; mt++) {
                    mma_bf16(c[mt][2 * p],     ah[mt], bl[p][0], bl[p][1]);
                    mma_bf16(c[mt][2 * p + 1], ah[mt], bl[p][2], bl[p][3]);
                }
            // pass 3: Al*Bh
#pragma unroll
            for (int p = 0; p < 2; p++)
#pragma unroll
                for (int mt = 0; mt < 4; mt++) {
                    mma_bf16(c[mt][2 * p],     al[mt], bh[p][0], bh[p][1]);
                    mma_bf16(c[mt][2 * p + 1], al[mt], bh[p][2], bh[p][3]);
                }
        }
    }

    // ---- epilogues ----
    const int batch = rowBase / SS;
    if (mode <= 1) {
        __nv_bfloat16* Oh = (mode == 0) ? g_Qh : g_Kh;
        __nv_bfloat16* Ol = (mode == 0) ? g_Ql : g_Kl;
        const float sc = (mode == 0) ? 0.25f * 1.44269504089f : 2.0f;
        const float* Aux = (mode == 0) ? AuxQ : AuxK;
#pragma unroll
        for (int mt = 0; mt < 4; mt++) {
            size_t row0 = (size_t)rowBase + wm * 64 + mt * 16 + g;
#pragma unroll
            for (int nt = 0; nt < 4; nt++) {
                int col = colBase + wn * 32 + nt * 8 + 2 * tig;
                float2 gv = *(const float2*)(Aux + (size_t)batch * EE + col);
                float gx = gv.x * sc, gy = gv.y * sc;
                uint32_t h, l;
                split2(c[mt][nt][0] * gx, c[mt][nt][1] * gy, h, l);
                *(uint32_t*)(Oh + row0 * EE + col) = h;
                *(uint32_t*)(Ol + row0 * EE + col) = l;
                split2(c[mt][nt][2] * gx, c[mt][nt][3] * gy, h, l);
                *(uint32_t*)(Oh + (row0 + 8) * EE + col) = h;
                *(uint32_t*)(Ol + (row0 + 8) * EE + col) = l;
            }
        }
    } else if (mode == 2) {
#pragma unroll
        for (int mt = 0; mt < 4; mt++) {
            int row0 = rowBase + wm * 64 + mt * 16 + g;
            int s = row0 - batch * SS;
#pragma unroll
            for (int nt = 0; nt < 4; nt++) {
                int col = colBase + wn * 32 + nt * 8 + 2 * tig;
                int hh = col >> 6, d = col & 63;
                size_t vb = ((size_t)(batch * HH + hh) * 64 + d) * SS + s;
                __nv_bfloat16 h, l;
                split1(c[mt][nt][0], h, l); g_Vth[vb] = h;          g_Vtl[vb] = l;
                split1(c[mt][nt][1], h, l); g_Vth[vb + SS] = h;     g_Vtl[vb + SS] = l;
                split1(c[mt][nt][2], h, l); g_Vth[vb + 8] = h;      g_Vtl[vb + 8] = l;
                split1(c[mt][nt][3], h, l); g_Vth[vb + SS + 8] = h; g_Vtl[vb + SS + 8] = l;
            }
        }
    } else {
#pragma unroll
        for (int mt = 0; mt < 4; mt++) {
            size_t row0 = (size_t)rowBase + wm * 64 + mt * 16 + g;
#pragma unroll
            for (int nt = 0; nt < 4; nt++) {
                int col = colBase + wn * 32 + nt * 8 + 2 * tig;
                float2 x0 = *(const float2*)(AuxX + row0 * EE + col);
                float2 x1 = *(const float2*)(AuxX + (row0 + 8) * EE + col);
                *(float2*)(g_R + row0 * EE + col) =
                    make_float2(c[mt][nt][0] + x0.x, c[mt][nt][1] + x0.y);
                *(float2*)(g_R + (row0 + 8) * EE + col) =
                    make_float2(c[mt][nt][2] + x1.x, c[mt][nt][3] + x1.y);
            }
        }
    }
}

// ---------------- tensor-core flash attention (128 thr, 2 CTAs/SM) ----------
#define AROW 144
#define ATILE (64 * AROW)
#define ABUF (4 * ATILE)
#define ATTN_SMEM (2 * ABUF)               /* 73728 per CTA */

__global__ __launch_bounds__(128, 2) void attn_kernel()
{
    extern __shared__ char smb[];
    const uint32_t sbase = smem_u32(smb);

    const int qt = blockIdx.x;     // 0..15 (64 q rows each)
    const int h  = blockIdx.y;
    const int b  = blockIdx.z;
    const int tid = threadIdx.x;
    const int wid = tid >> 5;      // 0..3
    const int lane = tid & 31;
    const int g = lane >> 2;
    const int tig = lane & 3;

    const size_t kbase0 = ((size_t)b * SS) * EE + h * 64;
    const size_t vbase0 = ((size_t)(b * HH + h) * 64) * SS;

    auto issue = [&](int kt, int stage) {
        uint32_t sb = sbase + stage * ABUF;
#pragma unroll
        for (int i = 0; i < 4; i++) {
            int ch = tid + i * 128;        // 0..511
            int r = ch >> 3;               // 0..63
            int cb = (ch & 7) * 16;
            int c8 = (ch & 7) * 8;
            size_t ko = kbase0 + (size_t)(kt * 64 + r) * EE + c8;
            size_t vo = vbase0 + (size_t)r * SS + kt * 64 + c8;
            uint32_t off = r * AROW + cb;
            cp16(sb + off,             g_Kh + ko);
            cp16(sb + ATILE + off,     g_Kl + ko);
            cp16(sb + 2 * ATILE + off, g_Vth + vo);
            cp16(sb + 3 * ATILE + off, g_Vtl + vo);
        }
        CP_COMMIT;
    };

    issue(0, 0);

    // ---- Q fragments (held all kernel; log2e pre-folded) ----
    uint32_t qh[4][4], ql[4][4];
    {
        size_t rg = (size_t)(b * SS + qt * 64 + wid * 16 + g);
        const __nv_bfloat16* ph = g_Qh + rg * EE + h * 64;
        const __nv_bfloat16* pl = g_Ql + rg * EE + h * 64;
#pragma unroll
        for (int ks = 0; ks < 4; ks++) {
            int c0 = ks * 16 + 2 * tig;
            qh[ks][0] = *(const uint32_t*)(ph + c0);
            qh[ks][1] = *(const uint32_t*)(ph + 8 * EE + c0);
            qh[ks][2] = *(const uint32_t*)(ph + c0 + 8);
            qh[ks][3] = *(const uint32_t*)(ph + 8 * EE + c0 + 8);
            ql[ks][0] = *(const uint32_t*)(pl + c0);
            ql[ks][1] = *(const uint32_t*)(pl + 8 * EE + c0);
            ql[ks][2] = *(const uint32_t*)(pl + c0 + 8);
            ql[ks][3] = *(const uint32_t*)(pl + 8 * EE + c0 + 8);
        }
    }

    float acc[8][4];
#pragma unroll
    for (int j = 0; j < 8; j++)
#pragma unroll
        for (int r = 0; r < 4; r++) acc[j][r] = 0.f;
    float m0 = -1e30f, m1 = -1e30f, l0 = 0.f, l1 = 0.f;

    const uint32_t fLane = (uint32_t)((lane & 7) + ((lane >> 4) & 1) * 8) * AROW
                         + ((lane >> 3) & 1) * 16;

    for (int kt = 0; kt < 16; kt++) {
        CP_WAIT(0);
        __syncthreads();
        if (kt < 15) issue(kt + 1, (kt + 1) & 1);

        const uint32_t sb = sbase + (kt & 1) * ABUF;
        const uint32_t kOff = sb + fLane;
        const uint32_t vOff = sb + 2 * ATILE + fLane;

        // ---- scores (log2 domain) ----
        float c[8][4];
#pragma unroll
        for (int j = 0; j < 8; j++)
#pragma unroll
            for (int r = 0; r < 4; r++) c[j][r] = 0.f;

#pragma unroll
        for (int ks = 0; ks < 4; ks++) {
            uint32_t bh[4][4], bl[4][4];
#pragma unroll
            for (int p = 0; p < 4; p++) {
                ldsm4(bh[p], kOff + p * 16 * AROW + ks * 32);
                ldsm4(bl[p], kOff + ATILE + p * 16 * AROW + ks * 32);
            }
#pragma unroll
            for (int p = 0; p < 4; p++) {
                mma_bf16(c[2 * p],     qh[ks], bh[p][0], bh[p][1]);
                mma_bf16(c[2 * p + 1], qh[ks], bh[p][2], bh[p][3]);
            }
#pragma unroll
            for (int p = 0; p < 4; p++) {
                mma_bf16(c[2 * p],     qh[ks], bl[p][0], bl[p][1]);
                mma_bf16(c[2 * p + 1], qh[ks], bl[p][2], bl[p][3]);
            }
#pragma unroll
            for (int p = 0; p < 4; p++) {
                mma_bf16(c[2 * p],     ql[ks], bh[p][0], bh[p][1]);
                mma_bf16(c[2 * p + 1], ql[ks], bh[p][2], bh[p][3]);
            }
        }

        // ---- online softmax (exp2 domain) ----
        float mx0 = -1e30f, mx1 = -1e30f;
#pragma unroll
        for (int j = 0; j < 8; j++) {
            mx0 = fmaxf(mx0, fmaxf(c[j][0], c[j][1]));
            mx1 = fmaxf(mx1, fmaxf(c[j][2], c[j][3]));
        }
        mx0 = fmaxf(mx0, __shfl_xor_sync(0xffffffffu, mx0, 1));
        mx0 = fmaxf(mx0, __shfl_xor_sync(0xffffffffu, mx0, 2));
        mx1 = fmaxf(mx1, __shfl_xor_sync(0xffffffffu, mx1, 1));
        mx1 = fmaxf(mx1, __shfl_xor_sync(0xffffffffu, mx1, 2));
        float mn0 = fmaxf(m0, mx0), mn1 = fmaxf(m1, mx1);
        float cr0 = exp2f(m0 - mn0), cr1 = exp2f(m1 - mn1);
        float s0 = 0.f, s1 = 0.f;
#pragma unroll
        for (int j = 0; j < 8; j++) {
            c[j][0] = exp2f(c[j][0] - mn0);
            c[j][1] = exp2f(c[j][1] - mn0);
            c[j][2] = exp2f(c[j][2] - mn1);
            c[j][3] = exp2f(c[j][3] - mn1);
            s0 += c[j][0] + c[j][1];
            s1 += c[j][2] + c[j][3];
        }
        s0 += __shfl_xor_sync(0xffffffffu, s0, 1);
        s0 += __shfl_xor_sync(0xffffffffu, s0, 2);
        s1 += __shfl_xor_sync(0xffffffffu, s1, 1);
        s1 += __shfl_xor_sync(0xffffffffu, s1, 2);
        l0 = l0 * cr0 + s0;
        l1 = l1 * cr1 + s1;
        m0 = mn0; m1 = mn1;
#pragma unroll
        for (int j = 0; j < 8; j++) {
            acc[j][0] *= cr0; acc[j][1] *= cr0;
            acc[j][2] *= cr1; acc[j][3] *= cr1;
        }

        // ---- PV: term-major within each ks ----
#pragma unroll
        for (int ks = 0; ks < 4; ks++) {
            uint32_t ph[4], pl[4];
            split2(c[2 * ks][0],     c[2 * ks][1],     ph[0], pl[0]);
            split2(c[2 * ks][2],     c[2 * ks][3],     ph[1], pl[1]);
            split2(c[2 * ks + 1][0], c[2 * ks + 1][1], ph[2], pl[2]);
            split2(c[2 * ks + 1][2], c[2 * ks + 1][3], ph[3], pl[3]);
            uint32_t vh[4][4], vl[4][4];
#pragma unroll
            for (int p = 0; p < 4; p++) {
                ldsm4(vh[p], vOff + p * 16 * AROW + ks * 32);
                ldsm4(vl[p], vOff + ATILE + p * 16 * AROW + ks * 32);
            }
#pragma unroll
            for (int p = 0; p < 4; p++) {
                mma_bf16(acc[2 * p],     ph, vh[p][0], vh[p][1]);
                mma_bf16(acc[2 * p + 1], ph, vh[p][2], vh[p][3]);
            }
#pragma unroll
            for (int p = 0; p < 4; p++) {
                mma_bf16(acc[2 * p],     ph, vl[p][0], vl[p][1]);
                mma_bf16(acc[2 * p + 1], ph, vl[p][2], vl[p][3]);
            }
#pragma unroll
            for (int p = 0; p < 4; p++) {
                mma_bf16(acc[2 * p],     pl, vh[p][0], vh[p][1]);
                mma_bf16(acc[2 * p + 1], pl, vh[p][2], vh[p][3]);
            }
        }
    }

    // ---- epilogue ----
    float i0 = 1.f / l0, i1 = 1.f / l1;
    size_t rg = (size_t)(b * SS + qt * 64 + wid * 16 + g);
#pragma unroll
    for (int j = 0; j < 8; j++) {
        int col = h * 64 + j * 8 + 2 * tig;
        uint32_t hh, ll;
        split2(acc[j][0] * i0, acc[j][1] * i0, hh, ll);
        *(uint32_t*)(g_Oh + rg * EE + col) = hh;
        *(uint32_t*)(g_Ol + rg * EE + col) = ll;
        split2(acc[j][2] * i1, acc[j][3] * i1, hh, ll);
        *(uint32_t*)(g_Oh + (rg + 8) * EE + col) = hh;
        *(uint32_t*)(g_Ol + (rg + 8) * EE + col) = ll;
    }
}

// ---------------- LayerNorm ----------------
__global__ __launch_bounds__(256) void ln_kernel(
    const float* __restrict__ gamma, const float* __restrict__ beta,
    float* __restrict__ out)
{
    const int row = blockIdx.x;
    const int tid = threadIdx.x;
    const float4 v = *(const float4*)(g_R + (size_t)row * EE + tid * 4);

    float s1 = v.x + v.y + v.z + v.w;
    float s2 = v.x * v.x + v.y * v.y + v.z * v.z + v.w * v.w;

    __shared__ float sh1[8], sh2[8];
#pragma unroll
    for (int off = 16; off > 0; off >>= 1) {
        s1 += __shfl_xor_sync(0xffffffffu, s1, off);
        s2 += __shfl_xor_sync(0xffffffffu, s2, off);
    }
    const int warp = tid >> 5;
    if ((tid & 31) == 0) { sh1[warp] = s1; sh2[warp] = s2; }
    __syncthreads();
    float t1 = 0.f, t2 = 0.f;
#pragma unroll
    for (int w = 0; w < 8; w++) { t1 += sh1[w]; t2 += sh2[w]; }

    const float mean = t1 * (1.0f / EE);
    const float var  = t2 * (1.0f / EE) - mean * mean;
    const float inv  = rsqrtf(var + 1e-6f);

    const float4 gmv = *(const float4*)(gamma + tid * 4);
    const float4 btv = *(const float4*)(beta + tid * 4);
    float4 o;
    o.x = (v.x - mean) * inv * gmv.x + btv.x;
    o.y = (v.y - mean) * inv * gmv.y + btv.y;
    o.z = (v.z - mean) * inv * gmv.z + btv.z;
    o.w = (v.w - mean) * inv * gmv.w + btv.w;
    *(float4*)(out + (size_t)row * EE + tid * 4) = o;
}

// ---------------------------------------------------------------------------
extern "C" void kernel_launch(void* const* d_in, const int* in_sizes, int n_in,
                              void* d_out, int out_size)
{
    const float* X     = (const float*)d_in[0];
    const float* gQ    = (const float*)d_in[1];
    const float* gK    = (const float*)d_in[2];
    const float* Wq    = (const float*)d_in[3];
    const float* Wk    = (const float*)d_in[4];
    const float* Wv    = (const float*)d_in[5];
    const float* Wo    = (const float*)d_in[6];
    const float* gamma = (const float*)d_in[7];
    const float* beta  = (const float*)d_in[8];
    float* out = (float*)d_out;

    cudaFuncSetAttribute(gemm_kernel,
                         cudaFuncAttributeMaxDynamicSharedMemorySize, GEMM_SMEM);
    cudaFuncSetAttribute(attn_kernel,
                         cudaFuncAttributeMaxDynamicSharedMemorySize, ATTN_SMEM);

    prep_x_kernel<<<NELEM / 1024, 256>>>(X);
    prep_w_kernel<<<dim3(32, 32, 4), dim3(32, 8)>>>(Wq, Wk, Wv, Wo);

    gemm_kernel<<<dim3(16, 64, 3), 128, GEMM_SMEM>>>(gQ, gK, X, 0);

    attn_kernel<<<dim3(16, HH, BB), 128, ATTN_SMEM>>>();

    gemm_kernel<<<dim3(16, 64, 1), 128, GEMM_SMEM>>>(gQ, gK, X, 3);
    ln_kernel<<<M_TOT, 256>>>(gamma, beta, out);
}

// round 8
// speedup vs baseline: 3.4100x; 1.1556x over previous
#include <cuda_runtime.h>
#include <cuda_fp16.h>
#include <stdint.h>

#define BB 8
#define SS 1024
#define EE 1024
#define HH 16
#define M_TOT 8192
#define NELEM ((size_t)M_TOT * EE)   /* 8388608 */

// ---------------- scratch (device globals; no allocations) ----------------
__device__ __half g_Xh[NELEM], g_Xl[NELEM];
__device__ __half g_Wth[4 * 1048576], g_Wtl[4 * 1048576];  // [N][K], scaled x32
__device__ __half g_Qh[NELEM], g_Ql[NELEM];   // gate*2*0.125*log2e folded
__device__ __half g_Kh[NELEM], g_Kl[NELEM];   // gate*2 folded
__device__ __half g_Vt[NELEM];                // [(b*H+h)*64+d][s], single fp16
__device__ __half g_Oh[NELEM], g_Ol[NELEM];
__device__ float g_R[NELEM];

// ---------------- helpers ----------------
__device__ __forceinline__ void mma_f16(float* c, const uint32_t* a,
                                        uint32_t b0, uint32_t b1) {
    asm volatile(
        "mma.sync.aligned.m16n8k16.row.col.f32.f16.f16.f32 "
        "{%0,%1,%2,%3}, {%4,%5,%6,%7}, {%8,%9}, {%0,%1,%2,%3};"
        : "+f"(c[0]), "+f"(c[1]), "+f"(c[2]), "+f"(c[3])
        : "r"(a[0]), "r"(a[1]), "r"(a[2]), "r"(a[3]), "r"(b0), "r"(b1));
}

__device__ __forceinline__ void ldsm4(uint32_t* r, uint32_t addr) {
    asm volatile("ldmatrix.sync.aligned.m8n8.x4.shared.b16 {%0,%1,%2,%3}, [%4];"
                 : "=r"(r[0]), "=r"(r[1]), "=r"(r[2]), "=r"(r[3]) : "r"(addr));
}

__device__ __forceinline__ void cp16(uint32_t s, const void* g) {
    asm volatile("cp.async.cg.shared.global [%0], [%1], 16;" :: "r"(s), "l"(g));
}
#define CP_COMMIT asm volatile("cp.async.commit_group;" ::: "memory")
#define CP_WAIT(n) asm volatile("cp.async.wait_group %0;" :: "n"(n) : "memory")

__device__ __forceinline__ uint32_t smem_u32(const void* p) {
    uint32_t a;
    asm("{ .reg .u64 t; cvta.to.shared.u64 t, %1; cvt.u32.u64 %0, t; }"
        : "=r"(a) : "l"(p));
    return a;
}

__device__ __forceinline__ void split2(float x, float y, uint32_t& h, uint32_t& l) {
    __half2 hh = __floats2half2_rn(x, y);
    __half2 ll = __floats2half2_rn(x - __low2float(hh), y - __high2float(hh));
    h = *(uint32_t*)&hh;
    l = *(uint32_t*)&ll;
}

__device__ __forceinline__ uint32_t packh2(float x, float y) {
    __half2 hh = __floats2half2_rn(x, y);
    return *(uint32_t*)&hh;
}

__device__ __forceinline__ void split1(float x, __half& h, __half& l) {
    h = __float2half_rn(x);
    l = __float2half_rn(x - __half2float(h));
}

// ---------------- prep: split X into fp16 hi/lo ----------------
__global__ __launch_bounds__(256) void prep_x_kernel(const float* __restrict__ X)
{
    size_t i = ((size_t)blockIdx.x * 256 + threadIdx.x) * 4;
    float4 v = *(const float4*)(X + i);
    uint32_t h01, l01, h23, l23;
    split2(v.x, v.y, h01, l01);
    split2(v.z, v.w, h23, l23);
    *(uint32_t*)(g_Xh + i)     = h01;
    *(uint32_t*)(g_Xh + i + 2) = h23;
    *(uint32_t*)(g_Xl + i)     = l01;
    *(uint32_t*)(g_Xl + i + 2) = l23;
}

// ---------------- prep: weights x32 -> K-major fp16 hi/lo ----------------
__global__ __launch_bounds__(256) void prep_w_kernel(
    const float* __restrict__ Wq, const float* __restrict__ Wk,
    const float* __restrict__ Wv, const float* __restrict__ Wo)
{
    const int which = blockIdx.z;
    const float* W = (which == 0) ? Wq : (which == 1) ? Wk : (which == 2) ? Wv : Wo;
    __half* Oh = g_Wth + (size_t)which * 1048576;
    __half* Ol = g_Wtl + (size_t)which * 1048576;

    __shared__ float tile[32][33];
    const int tx = threadIdx.x, ty = threadIdx.y;
    const int n0 = blockIdx.x * 32, k0 = blockIdx.y * 32;

    if (which < 3) {
#pragma unroll
        for (int i = 0; i < 4; i++)
            tile[ty + 8 * i][tx] = W[(size_t)(k0 + ty + 8 * i) * EE + n0 + tx];
        __syncthreads();
#pragma unroll
        for (int i = 0; i < 4; i++) {
            float v = tile[tx][ty + 8 * i] * 32.0f;
            __half h, l;
            split1(v, h, l);
            size_t o = (size_t)(n0 + ty + 8 * i) * EE + k0 + tx;
            Oh[o] = h; Ol[o] = l;
        }
    } else {
#pragma unroll
        for (int i = 0; i < 4; i++) {
            size_t o = (size_t)(n0 + ty + 8 * i) * EE + k0 + tx;
            float v = W[o] * 32.0f;
            __half h, l;
            split1(v, h, l);
            Oh[o] = h; Ol[o] = l;
        }
    }
}

// ---------------- GEMM: 64x64 warp tiles, CTA 128x128, 2 CTAs/SM ------------
#define GROW 80                            /* 64B data + 16 pad */
#define GTILE (128 * GROW)                 /* 10240 */
#define GSTAGE (4 * GTILE)                 /* Ah, Al, Bh, Bl = 40960 */
#define GEMM_SMEM (2 * GSTAGE)             /* 81920 */
#define INV32 0.03125f

__global__ __launch_bounds__(128, 2) void gemm_kernel(
    const float* __restrict__ AuxQ, const float* __restrict__ AuxK,
    const float* __restrict__ AuxX, int modeBase)
{
    extern __shared__ char smb[];
    const uint32_t sbase = smem_u32(smb);

    const int mode = modeBase + blockIdx.z;
    const __half* Ahp = (mode == 3) ? g_Oh : g_Xh;
    const __half* Alp = (mode == 3) ? g_Ol : g_Xl;
    const __half* Bhp = g_Wth + (size_t)mode * 1048576;
    const __half* Blp = g_Wtl + (size_t)mode * 1048576;

    const int tid = threadIdx.x;
    const int wid = tid >> 5;
    const int lane = tid & 31;
    const int g = lane >> 2;
    const int tig = lane & 3;
    const int wm = wid >> 1;       // 0..1 (64 rows each)
    const int wn = wid & 1;        // 0..1 (64 cols each)
    const int colBase = blockIdx.x * 128;
    const int rowBase = blockIdx.y * 128;

    float c[4][8][4];
#pragma unroll
    for (int mt = 0; mt < 4; mt++)
#pragma unroll
        for (int nt = 0; nt < 8; nt++)
#pragma unroll
            for (int r = 0; r < 4; r++) c[mt][nt][r] = 0.f;

    const uint32_t aLane = (uint32_t)(wm * 64 + (lane & 7) + ((lane >> 3) & 1) * 8) * GROW
                         + ((lane >> 4) & 1) * 16;
    const uint32_t bLane = (uint32_t)(wn * 64 + (lane & 7) + ((lane >> 4) & 1) * 8) * GROW
                         + ((lane >> 3) & 1) * 16;

    auto issue = [&](int kt, int stage) {
        uint32_t sb = sbase + stage * GSTAGE;
#pragma unroll
        for (int i = 0; i < 4; i++) {
            int ch = tid + i * 128;        // 512 chunks
            int r = ch >> 2;
            int cb = (ch & 3) * 16;
            int c8 = (ch & 3) * 8;
            size_t ao = (size_t)(rowBase + r) * EE + kt * 32 + c8;
            uint32_t off = r * GROW + cb;
            cp16(sb + off,         Ahp + ao);
            cp16(sb + GTILE + off, Alp + ao);
        }
#pragma unroll
        for (int i = 0; i < 4; i++) {
            int ch = tid + i * 128;
            int r = ch >> 2;
            int cb = (ch & 3) * 16;
            int c8 = (ch & 3) * 8;
            size_t bo = (size_t)(colBase + r) * EE + kt * 32 + c8;
            uint32_t off = r * GROW + cb;
            cp16(sb + 2 * GTILE + off, Bhp + bo);
            cp16(sb + 3 * GTILE + off, Blp + bo);
        }
        CP_COMMIT;
    };

    issue(0, 0);

    for (int kt = 0; kt < 32; kt++) {
        CP_WAIT(0);
        __syncthreads();
        if (kt + 1 < 32) issue(kt + 1, (kt + 1) & 1);

        const uint32_t sb = sbase + (kt & 1) * GSTAGE;
        const uint32_t aOff = sb + aLane;
        const uint32_t bOff = sb + 2 * GTILE + bLane;

#pragma unroll
        for (int ks = 0; ks < 2; ks++) {
            uint32_t ah[4][4], al[4][4], bh[4][4], bl[4][4];
#pragma unroll
            for (int mt = 0; mt < 4; mt++) {
                ldsm4(ah[mt], aOff + mt * 16 * GROW + ks * 32);
                ldsm4(al[mt], aOff + GTILE + mt * 16 * GROW + ks * 32);
            }
#pragma unroll
            for (int p = 0; p < 4; p++) {
                ldsm4(bh[p], bOff + p * 16 * GROW + ks * 32);
                ldsm4(bl[p], bOff + GTILE + p * 16 * GROW + ks * 32);
            }
            // pass 1: Ah*Bh — 32 independent MMAs
#pragma unroll
            for (int p = 0; p < 4; p++)
#pragma unroll
                for (int mt = 0; mt < 4; mt++) {
                    mma_f16(c[mt][2 * p],     ah[mt], bh[p][0], bh[p][1]);
                    mma_f16(c[mt][2 * p + 1], ah[mt], bh[p][2], bh[p][3]);
                }
            // pass 2: Ah*Bl
#pragma unroll
            for (int p = 0; p < 4; p++)
#pragma unroll
                for (int mt = 0; mt < 4; mt++) {
                    mma_f16(c[mt][2 * p],     ah[mt], bl[p][0], bl[p][1]);
                    mma_f16(c[mt][2 * p + 1], ah[mt], bl[p][2], bl[p][3]);
                }
            // pass 3: Al*Bh
#pragma unroll
            for (int p = 0; p < 4; p++)
#pragma unroll
                for (int mt = 0; mt < 4; mt++) {
                    mma_f16(c[mt][2 * p],     al[mt], bh[p][0], bh[p][1]);
                    mma_f16(c[mt][2 * p + 1], al[mt], bh[p][2], bh[p][3]);
                }
        }
    }

    // ---- epilogues (fold 1/32 from weight scaling) ----
    const int batch = rowBase / SS;
    if (mode <= 1) {
        __half* Oh = (mode == 0) ? g_Qh : g_Kh;
        __half* Ol = (mode == 0) ? g_Ql : g_Kl;
        const float sc = ((mode == 0) ? 0.25f * 1.44269504089f : 2.0f) * INV32;
        const float* Aux = (mode == 0) ? AuxQ : AuxK;
#pragma unroll
        for (int mt = 0; mt < 4; mt++) {
            size_t row0 = (size_t)rowBase + wm * 64 + mt * 16 + g;
#pragma unroll
            for (int nt = 0; nt < 8; nt++) {
                int col = colBase + wn * 64 + nt * 8 + 2 * tig;
                float2 gv = *(const float2*)(Aux + (size_t)batch * EE + col);
                float gx = gv.x * sc, gy = gv.y * sc;
                uint32_t h, l;
                split2(c[mt][nt][0] * gx, c[mt][nt][1] * gy, h, l);
                *(uint32_t*)(Oh + row0 * EE + col) = h;
                *(uint32_t*)(Ol + row0 * EE + col) = l;
                split2(c[mt][nt][2] * gx, c[mt][nt][3] * gy, h, l);
                *(uint32_t*)(Oh + (row0 + 8) * EE + col) = h;
                *(uint32_t*)(Ol + (row0 + 8) * EE + col) = l;
            }
        }
    } else if (mode == 2) {
#pragma unroll
        for (int mt = 0; mt < 4; mt++) {
            int row0 = rowBase + wm * 64 + mt * 16 + g;
            int s = row0 - batch * SS;
#pragma unroll
            for (int nt = 0; nt < 8; nt++) {
                int col = colBase + wn * 64 + nt * 8 + 2 * tig;
                int hh = col >> 6, d = col & 63;
                size_t vb = ((size_t)(batch * HH + hh) * 64 + d) * SS + s;
                g_Vt[vb]          = __float2half_rn(c[mt][nt][0] * INV32);
                g_Vt[vb + SS]     = __float2half_rn(c[mt][nt][1] * INV32);
                g_Vt[vb + 8]      = __float2half_rn(c[mt][nt][2] * INV32);
                g_Vt[vb + SS + 8] = __float2half_rn(c[mt][nt][3] * INV32);
            }
        }
    } else {
#pragma unroll
        for (int mt = 0; mt < 4; mt++) {
            size_t row0 = (size_t)rowBase + wm * 64 + mt * 16 + g;
#pragma unroll
            for (int nt = 0; nt < 8; nt++) {
                int col = colBase + wn * 64 + nt * 8 + 2 * tig;
                float2 x0 = *(const float2*)(AuxX + row0 * EE + col);
                float2 x1 = *(const float2*)(AuxX + (row0 + 8) * EE + col);
                *(float2*)(g_R + row0 * EE + col) =
                    make_float2(c[mt][nt][0] * INV32 + x0.x, c[mt][nt][1] * INV32 + x0.y);
                *(float2*)(g_R + (row0 + 8) * EE + col) =
                    make_float2(c[mt][nt][2] * INV32 + x1.x, c[mt][nt][3] * INV32 + x1.y);
            }
        }
    }
}

// ---------------- flash attention: fp16, PV single-term ----------------
#define AROW 144
#define ATILE (64 * AROW)                  /* 9216 */
#define ABUF (3 * ATILE)                   /* Kh, Kl, V = 27648 */
#define ATTN_SMEM (2 * ABUF)               /* 55296 */

__global__ __launch_bounds__(128, 2) void attn_kernel()
{
    extern __shared__ char smb[];
    const uint32_t sbase = smem_u32(smb);

    const int qt = blockIdx.x;     // 0..15 (64 q rows each)
    const int h  = blockIdx.y;
    const int b  = blockIdx.z;
    const int tid = threadIdx.x;
    const int wid = tid >> 5;      // 0..3
    const int lane = tid & 31;
    const int g = lane >> 2;
    const int tig = lane & 3;

    const size_t kbase0 = ((size_t)b * SS) * EE + h * 64;
    const size_t vbase0 = ((size_t)(b * HH + h) * 64) * SS;

    auto issue = [&](int kt, int stage) {
        uint32_t sb = sbase + stage * ABUF;
#pragma unroll
        for (int i = 0; i < 4; i++) {
            int ch = tid + i * 128;        // 0..511
            int r = ch >> 3;               // 0..63
            int cb = (ch & 7) * 16;
            int c8 = (ch & 7) * 8;
            size_t ko = kbase0 + (size_t)(kt * 64 + r) * EE + c8;
            size_t vo = vbase0 + (size_t)r * SS + kt * 64 + c8;
            uint32_t off = r * AROW + cb;
            cp16(sb + off,             g_Kh + ko);
            cp16(sb + ATILE + off,     g_Kl + ko);
            cp16(sb + 2 * ATILE + off, g_Vt + vo);
        }
        CP_COMMIT;
    };

    issue(0, 0);

    // ---- Q fragments (held all kernel; log2e pre-folded) ----
    uint32_t qh[4][4], ql[4][4];
    {
        size_t rg = (size_t)(b * SS + qt * 64 + wid * 16 + g);
        const __half* ph = g_Qh + rg * EE + h * 64;
        const __half* pl = g_Ql + rg * EE + h * 64;
#pragma unroll
        for (int ks = 0; ks < 4; ks++) {
            int c0 = ks * 16 + 2 * tig;
            qh[ks][0] = *(const uint32_t*)(ph + c0);
            qh[ks][1] = *(const uint32_t*)(ph + 8 * EE + c0);
            qh[ks][2] = *(const uint32_t*)(ph + c0 + 8);
            qh[ks][3] = *(const uint32_t*)(ph + 8 * EE + c0 + 8);
            ql[ks][0] = *(const uint32_t*)(pl + c0);
            ql[ks][1] = *(const uint32_t*)(pl + 8 * EE + c0);
            ql[ks][2] = *(const uint32_t*)(pl + c0 + 8);
            ql[ks][3] = *(const uint32_t*)(pl + 8 * EE + c0 + 8);
        }
    }

    float acc[8][4];
#pragma unroll
    for (int j = 0; j < 8; j++)
#pragma unroll
        for (int r = 0; r < 4; r++) acc[j][r] = 0.f;
    float m0 = -1e30f, m1 = -1e30f, l0 = 0.f, l1 = 0.f;

    const uint32_t fLane = (uint32_t)((lane & 7) + ((lane >> 4) & 1) * 8) * AROW
                         + ((lane >> 3) & 1) * 16;

    for (int kt = 0; kt < 16; kt++) {
        CP_WAIT(0);
        __syncthreads();
        if (kt < 15) issue(kt + 1, (kt + 1) & 1);

        const uint32_t sb = sbase + (kt & 1) * ABUF;
        const uint32_t kOff = sb + fLane;
        const uint32_t vOff = sb + 2 * ATILE + fLane;

        // ---- scores (log2 domain), fp16 3-term ----
        float c[8][4];
#pragma unroll
        for (int j = 0; j < 8; j++)
#pragma unroll
            for (int r = 0; r < 4; r++) c[j][r] = 0.f;

#pragma unroll
        for (int ks = 0; ks < 4; ks++) {
            uint32_t bh[4][4], bl[4][4];
#pragma unroll
            for (int p = 0; p < 4; p++) {
                ldsm4(bh[p], kOff + p * 16 * AROW + ks * 32);
                ldsm4(bl[p], kOff + ATILE + p * 16 * AROW + ks * 32);
            }
#pragma unroll
            for (int p = 0; p < 4; p++) {
                mma_f16(c[2 * p],     qh[ks], bh[p][0], bh[p][1]);
                mma_f16(c[2 * p + 1], qh[ks], bh[p][2], bh[p][3]);
            }
#pragma unroll
            for (int p = 0; p < 4; p++) {
                mma_f16(c[2 * p],     qh[ks], bl[p][0], bl[p][1]);
                mma_f16(c[2 * p + 1], qh[ks], bl[p][2], bl[p][3]);
            }
#pragma unroll
            for (int p = 0; p < 4; p++) {
                mma_f16(c[2 * p],     ql[ks], bh[p][0], bh[p][1]);
                mma_f16(c[2 * p + 1], ql[ks], bh[p][2], bh[p][3]);
            }
        }

        // ---- online softmax (exp2 domain) ----
        float mx0 = -1e30f, mx1 = -1e30f;
#pragma unroll
        for (int j = 0; j < 8; j++) {
            mx0 = fmaxf(mx0, fmaxf(c[j][0], c[j][1]));
            mx1 = fmaxf(mx1, fmaxf(c[j][2], c[j][3]));
        }
        mx0 = fmaxf(mx0, __shfl_xor_sync(0xffffffffu, mx0, 1));
        mx0 = fmaxf(mx0, __shfl_xor_sync(0xffffffffu, mx0, 2));
        mx1 = fmaxf(mx1, __shfl_xor_sync(0xffffffffu, mx1, 1));
        mx1 = fmaxf(mx1, __shfl_xor_sync(0xffffffffu, mx1, 2));
        float mn0 = fmaxf(m0, mx0), mn1 = fmaxf(m1, mx1);
        float cr0 = exp2f(m0 - mn0), cr1 = exp2f(m1 - mn1);
        float s0 = 0.f, s1 = 0.f;
#pragma unroll
        for (int j = 0; j < 8; j++) {
            c[j][0] = exp2f(c[j][0] - mn0);
            c[j][1] = exp2f(c[j][1] - mn0);
            c[j][2] = exp2f(c[j][2] - mn1);
            c[j][3] = exp2f(c[j][3] - mn1);
            s0 += c[j][0] + c[j][1];
            s1 += c[j][2] + c[j][3];
        }
        s0 += __shfl_xor_sync(0xffffffffu, s0, 1);
        s0 += __shfl_xor_sync(0xffffffffu, s0, 2);
        s1 += __shfl_xor_sync(0xffffffffu, s1, 1);
        s1 += __shfl_xor_sync(0xffffffffu, s1, 2);
        l0 = l0 * cr0 + s0;
        l1 = l1 * cr1 + s1;
        m0 = mn0; m1 = mn1;
#pragma unroll
        for (int j = 0; j < 8; j++) {
            acc[j][0] *= cr0; acc[j][1] *= cr0;
            acc[j][2] *= cr1; acc[j][3] *= cr1;
        }

        // ---- PV: single term, P and V fp16 ----
#pragma unroll
        for (int ks = 0; ks < 4; ks++) {
            uint32_t ph[4];
            ph[0] = packh2(c[2 * ks][0],     c[2 * ks][1]);
            ph[1] = packh2(c[2 * ks][2],     c[2 * ks][3]);
            ph[2] = packh2(c[2 * ks + 1][0], c[2 * ks + 1][1]);
            ph[3] = packh2(c[2 * ks + 1][2], c[2 * ks + 1][3]);
            uint32_t vh[4][4];
#pragma unroll
            for (int p = 0; p < 4; p++)
                ldsm4(vh[p], vOff + p * 16 * AROW + ks * 32);
#pragma unroll
            for (int p = 0; p < 4; p++) {
                mma_f16(acc[2 * p],     ph, vh[p][0], vh[p][1]);
                mma_f16(acc[2 * p + 1], ph, vh[p][2], vh[p][3]);
            }
        }
    }

    // ---- epilogue: O = acc/l, write fp16 hi/lo ----
    float i0 = 1.f / l0, i1 = 1.f / l1;
    size_t rg = (size_t)(b * SS + qt * 64 + wid * 16 + g);
#pragma unroll
    for (int j = 0; j < 8; j++) {
        int col = h * 64 + j * 8 + 2 * tig;
        uint32_t hh, ll;
        split2(acc[j][0] * i0, acc[j][1] * i0, hh, ll);
        *(uint32_t*)(g_Oh + rg * EE + col) = hh;
        *(uint32_t*)(g_Ol + rg * EE + col) = ll;
        split2(acc[j][2] * i1, acc[j][3] * i1, hh, ll);
        *(uint32_t*)(g_Oh + (rg + 8) * EE + col) = hh;
        *(uint32_t*)(g_Ol + (rg + 8) * EE + col) = ll;
    }
}

// ---------------- LayerNorm ----------------
__global__ __launch_bounds__(256) void ln_kernel(
    const float* __restrict__ gamma, const float* __restrict__ beta,
    float* __restrict__ out)
{
    const int row = blockIdx.x;
    const int tid = threadIdx.x;
    const float4 v = *(const float4*)(g_R + (size_t)row * EE + tid * 4);

    float s1 = v.x + v.y + v.z + v.w;
    float s2 = v.x * v.x + v.y * v.y + v.z * v.z + v.w * v.w;

    __shared__ float sh1[8], sh2[8];
#pragma unroll
    for (int off = 16; off > 0; off >>= 1) {
        s1 += __shfl_xor_sync(0xffffffffu, s1, off);
        s2 += __shfl_xor_sync(0xffffffffu, s2, off);
    }
    const int warp = tid >> 5;
    if ((tid & 31) == 0) { sh1[warp] = s1; sh2[warp] = s2; }
    __syncthreads();
    float t1 = 0.f, t2 = 0.f;
#pragma unroll
    for (int w = 0; w < 8; w++) { t1 += sh1[w]; t2 += sh2[w]; }

    const float mean = t1 * (1.0f / EE);
    const float var  = t2 * (1.0f / EE) - mean * mean;
    const float inv  = rsqrtf(var + 1e-6f);

    const float4 gmv = *(const float4*)(gamma + tid * 4);
    const float4 btv = *(const float4*)(beta + tid * 4);
    float4 o;
    o.x = (v.x - mean) * inv * gmv.x + btv.x;
    o.y = (v.y - mean) * inv * gmv.y + btv.y;
    o.z = (v.z - mean) * inv * gmv.z + btv.z;
    o.w = (v.w - mean) * inv * gmv.w + btv.w;
    *(float4*)(out + (size_t)row * EE + tid * 4) = o;
}

// ---------------------------------------------------------------------------
extern "C" void kernel_launch(void* const* d_in, const int* in_sizes, int n_in,
                              void* d_out, int out_size)
{
    const float* X     = (const float*)d_in[0];
    const float* gQ    = (const float*)d_in[1];
    const float* gK    = (const float*)d_in[2];
    const float* Wq    = (const float*)d_in[3];
    const float* Wk    = (const float*)d_in[4];
    const float* Wv    = (const float*)d_in[5];
    const float* Wo    = (const float*)d_in[6];
    const float* gamma = (const float*)d_in[7];
    const float* beta  = (const float*)d_in[8];
    float* out = (float*)d_out;

    cudaFuncSetAttribute(gemm_kernel,
                         cudaFuncAttributeMaxDynamicSharedMemorySize, GEMM_SMEM);
    cudaFuncSetAttribute(attn_kernel,
                         cudaFuncAttributeMaxDynamicSharedMemorySize, ATTN_SMEM);

    prep_x_kernel<<<NELEM / 1024, 256>>>(X);
    prep_w_kernel<<<dim3(32, 32, 4), dim3(32, 8)>>>(Wq, Wk, Wv, Wo);

    gemm_kernel<<<dim3(8, 64, 3), 128, GEMM_SMEM>>>(gQ, gK, X, 0);

    attn_kernel<<<dim3(16, HH, BB), 128, ATTN_SMEM>>>();

    gemm_kernel<<<dim3(8, 64, 1), 128, GEMM_SMEM>>>(gQ, gK, X, 3);
    ln_kernel<<<M_TOT, 256>>>(gamma, beta, out);
}

// round 9
// speedup vs baseline: 4.0978x; 1.2017x over previous
#include <cuda_runtime.h>
#include <cuda_fp16.h>
#include <stdint.h>

#define BB 8
#define SS 1024
#define EE 1024
#define HH 16
#define M_TOT 8192
#define NELEM ((size_t)M_TOT * EE)   /* 8388608 */

// ---------------- scratch (device globals; no allocations) ----------------
__device__ __half g_Xh[NELEM], g_Xl[NELEM];
__device__ __half g_Wth[4 * 1048576], g_Wtl[4 * 1048576];  // [N][K], scaled x32
__device__ __half g_Qh[NELEM], g_Ql[NELEM];   // gate*2*0.125*log2e folded
__device__ __half g_Kh[NELEM], g_Kl[NELEM];   // gate*2 folded
__device__ __half g_Vt[NELEM];                // [(b*H+h)*64+d][s], single fp16
__device__ __half g_Oh[NELEM], g_Ol[NELEM];
__device__ float g_R[NELEM];

// ---------------- helpers ----------------
__device__ __forceinline__ void mma_f16(float* c, const uint32_t* a,
                                        uint32_t b0, uint32_t b1) {
    asm volatile(
        "mma.sync.aligned.m16n8k16.row.col.f32.f16.f16.f32 "
        "{%0,%1,%2,%3}, {%4,%5,%6,%7}, {%8,%9}, {%0,%1,%2,%3};"
        : "+f"(c[0]), "+f"(c[1]), "+f"(c[2]), "+f"(c[3])
        : "r"(a[0]), "r"(a[1]), "r"(a[2]), "r"(a[3]), "r"(b0), "r"(b1));
}

__device__ __forceinline__ void ldsm4(uint32_t* r, uint32_t addr) {
    asm volatile("ldmatrix.sync.aligned.m8n8.x4.shared.b16 {%0,%1,%2,%3}, [%4];"
                 : "=r"(r[0]), "=r"(r[1]), "=r"(r[2]), "=r"(r[3]) : "r"(addr));
}

__device__ __forceinline__ void cp16(uint32_t s, const void* g) {
    asm volatile("cp.async.cg.shared.global [%0], [%1], 16;" :: "r"(s), "l"(g));
}
#define CP_COMMIT asm volatile("cp.async.commit_group;" ::: "memory")
#define CP_WAIT(n) asm volatile("cp.async.wait_group %0;" :: "n"(n) : "memory")

__device__ __forceinline__ uint32_t smem_u32(const void* p) {
    uint32_t a;
    asm("{ .reg .u64 t; cvta.to.shared.u64 t, %1; cvt.u32.u64 %0, t; }"
        : "=r"(a) : "l"(p));
    return a;
}

__device__ __forceinline__ void split2(float x, float y, uint32_t& h, uint32_t& l) {
    __half2 hh = __floats2half2_rn(x, y);
    __half2 ll = __floats2half2_rn(x - __low2float(hh), y - __high2float(hh));
    h = *(uint32_t*)&hh;
    l = *(uint32_t*)&ll;
}

__device__ __forceinline__ uint32_t packh2(float x, float y) {
    __half2 hh = __floats2half2_rn(x, y);
    return *(uint32_t*)&hh;
}

__device__ __forceinline__ void split1(float x, __half& h, __half& l) {
    h = __float2half_rn(x);
    l = __float2half_rn(x - __half2float(h));
}

// ---------------- prep: split X into fp16 hi/lo ----------------
__global__ __launch_bounds__(256) void prep_x_kernel(const float* __restrict__ X)
{
    size_t i = ((size_t)blockIdx.x * 256 + threadIdx.x) * 4;
    float4 v = *(const float4*)(X + i);
    uint32_t h01, l01, h23, l23;
    split2(v.x, v.y, h01, l01);
    split2(v.z, v.w, h23, l23);
    *(uint32_t*)(g_Xh + i)     = h01;
    *(uint32_t*)(g_Xh + i + 2) = h23;
    *(uint32_t*)(g_Xl + i)     = l01;
    *(uint32_t*)(g_Xl + i + 2) = l23;
}

// ---------------- prep: weights x32 -> K-major fp16 hi/lo ----------------
__global__ __launch_bounds__(256) void prep_w_kernel(
    const float* __restrict__ Wq, const float* __restrict__ Wk,
    const float* __restrict__ Wv, const float* __restrict__ Wo)
{
    const int which = blockIdx.z;
    const float* W = (which == 0) ? Wq : (which == 1) ? Wk : (which == 2) ? Wv : Wo;
    __half* Oh = g_Wth + (size_t)which * 1048576;
    __half* Ol = g_Wtl + (size_t)which * 1048576;

    __shared__ float tile[32][33];
    const int tx = threadIdx.x, ty = threadIdx.y;
    const int n0 = blockIdx.x * 32, k0 = blockIdx.y * 32;

    if (which < 3) {
#pragma unroll
        for (int i = 0; i < 4; i++)
            tile[ty + 8 * i][tx] = W[(size_t)(k0 + ty + 8 * i) * EE + n0 + tx];
        __syncthreads();
#pragma unroll
        for (int i = 0; i < 4; i++) {
            float v = tile[tx][ty + 8 * i] * 32.0f;
            __half h, l;
            split1(v, h, l);
            size_t o = (size_t)(n0 + ty + 8 * i) * EE + k0 + tx;
            Oh[o] = h; Ol[o] = l;
        }
    } else {
#pragma unroll
        for (int i = 0; i < 4; i++) {
            size_t o = (size_t)(n0 + ty + 8 * i) * EE + k0 + tx;
            float v = W[o] * 32.0f;
            __half h, l;
            split1(v, h, l);
            Oh[o] = h; Ol[o] = l;
        }
    }
}

// ---------------- GEMM: 64x64 warp tiles, CTA 128x128, 2 CTAs/SM ------------
// modes 0,1 (Q,K): 3-term. modes 2,3 (V,out-proj): 2-term (B_lo dropped).
#define GROW 80                            /* 64B data + 16 pad */
#define GTILE (128 * GROW)                 /* 10240 */
#define GSTAGE (4 * GTILE)                 /* Ah, Al, Bh, Bl = 40960 */
#define GEMM_SMEM (2 * GSTAGE)             /* 81920 */
#define INV32 0.03125f

__global__ __launch_bounds__(128, 2) void gemm_kernel(
    const float* __restrict__ AuxQ, const float* __restrict__ AuxK,
    const float* __restrict__ AuxX, int modeBase)
{
    extern __shared__ char smb[];
    const uint32_t sbase = smem_u32(smb);

    const int mode = modeBase + blockIdx.z;
    const bool threeTerm = (mode <= 1);
    const __half* Ahp = (mode == 3) ? g_Oh : g_Xh;
    const __half* Alp = (mode == 3) ? g_Ol : g_Xl;
    const __half* Bhp = g_Wth + (size_t)mode * 1048576;
    const __half* Blp = g_Wtl + (size_t)mode * 1048576;

    const int tid = threadIdx.x;
    const int wid = tid >> 5;
    const int lane = tid & 31;
    const int g = lane >> 2;
    const int tig = lane & 3;
    const int wm = wid >> 1;       // 0..1 (64 rows each)
    const int wn = wid & 1;        // 0..1 (64 cols each)
    const int colBase = blockIdx.x * 128;
    const int rowBase = blockIdx.y * 128;

    float c[4][8][4];
#pragma unroll
    for (int mt = 0; mt < 4; mt++)
#pragma unroll
        for (int nt = 0; nt < 8; nt++)
#pragma unroll
            for (int r = 0; r < 4; r++) c[mt][nt][r] = 0.f;

    const uint32_t aLane = (uint32_t)(wm * 64 + (lane & 7) + ((lane >> 3) & 1) * 8) * GROW
                         + ((lane >> 4) & 1) * 16;
    const uint32_t bLane = (uint32_t)(wn * 64 + (lane & 7) + ((lane >> 4) & 1) * 8) * GROW
                         + ((lane >> 3) & 1) * 16;

    auto issue = [&](int kt, int stage) {
        uint32_t sb = sbase + stage * GSTAGE;
#pragma unroll
        for (int i = 0; i < 4; i++) {
            int ch = tid + i * 128;        // 512 chunks
            int r = ch >> 2;
            int cb = (ch & 3) * 16;
            int c8 = (ch & 3) * 8;
            size_t ao = (size_t)(rowBase + r) * EE + kt * 32 + c8;
            uint32_t off = r * GROW + cb;
            cp16(sb + off,         Ahp + ao);
            cp16(sb + GTILE + off, Alp + ao);
        }
#pragma unroll
        for (int i = 0; i < 4; i++) {
            int ch = tid + i * 128;
            int r = ch >> 2;
            int cb = (ch & 3) * 16;
            int c8 = (ch & 3) * 8;
            size_t bo = (size_t)(colBase + r) * EE + kt * 32 + c8;
            uint32_t off = r * GROW + cb;
            cp16(sb + 2 * GTILE + off, Bhp + bo);
            if (threeTerm)
                cp16(sb + 3 * GTILE + off, Blp + bo);
        }
        CP_COMMIT;
    };

    issue(0, 0);

    for (int kt = 0; kt < 32; kt++) {
        CP_WAIT(0);
        __syncthreads();
        if (kt + 1 < 32) issue(kt + 1, (kt + 1) & 1);

        const uint32_t sb = sbase + (kt & 1) * GSTAGE;
        const uint32_t aOff = sb + aLane;
        const uint32_t bOff = sb + 2 * GTILE + bLane;

#pragma unroll
        for (int ks = 0; ks < 2; ks++) {
            uint32_t ah[4][4], al[4][4], bh[4][4];
#pragma unroll
            for (int mt = 0; mt < 4; mt++) {
                ldsm4(ah[mt], aOff + mt * 16 * GROW + ks * 32);
                ldsm4(al[mt], aOff + GTILE + mt * 16 * GROW + ks * 32);
            }
#pragma unroll
            for (int p = 0; p < 4; p++)
                ldsm4(bh[p], bOff + p * 16 * GROW + ks * 32);
            // pass 1: Ah*Bh — 32 independent MMAs
#pragma unroll
            for (int p = 0; p < 4; p++)
#pragma unroll
                for (int mt = 0; mt < 4; mt++) {
                    mma_f16(c[mt][2 * p],     ah[mt], bh[p][0], bh[p][1]);
                    mma_f16(c[mt][2 * p + 1], ah[mt], bh[p][2], bh[p][3]);
                }
            // pass 2: Al*Bh
#pragma unroll
            for (int p = 0; p < 4; p++)
#pragma unroll
                for (int mt = 0; mt < 4; mt++) {
                    mma_f16(c[mt][2 * p],     al[mt], bh[p][0], bh[p][1]);
                    mma_f16(c[mt][2 * p + 1], al[mt], bh[p][2], bh[p][3]);
                }
            // pass 3: Ah*Bl (Q,K only)
            if (threeTerm) {
                uint32_t bl[4][4];
#pragma unroll
                for (int p = 0; p < 4; p++)
                    ldsm4(bl[p], bOff + GTILE + p * 16 * GROW + ks * 32);
#pragma unroll
                for (int p = 0; p < 4; p++)
#pragma unroll
                    for (int mt = 0; mt < 4; mt++) {
                        mma_f16(c[mt][2 * p],     ah[mt], bl[p][0], bl[p][1]);
                        mma_f16(c[mt][2 * p + 1], ah[mt], bl[p][2], bl[p][3]);
                    }
            }
        }
    }

    // ---- epilogues (fold 1/32 from weight scaling) ----
    const int batch = rowBase / SS;
    if (mode <= 1) {
        __half* Oh = (mode == 0) ? g_Qh : g_Kh;
        __half* Ol = (mode == 0) ? g_Ql : g_Kl;
        const float sc = ((mode == 0) ? 0.25f * 1.44269504089f : 2.0f) * INV32;
        const float* Aux = (mode == 0) ? AuxQ : AuxK;
#pragma unroll
        for (int mt = 0; mt < 4; mt++) {
            size_t row0 = (size_t)rowBase + wm * 64 + mt * 16 + g;
#pragma unroll
            for (int nt = 0; nt < 8; nt++) {
                int col = colBase + wn * 64 + nt * 8 + 2 * tig;
                float2 gv = *(const float2*)(Aux + (size_t)batch * EE + col);
                float gx = gv.x * sc, gy = gv.y * sc;
                uint32_t h, l;
                split2(c[mt][nt][0] * gx, c[mt][nt][1] * gy, h, l);
                *(uint32_t*)(Oh + row0 * EE + col) = h;
                *(uint32_t*)(Ol + row0 * EE + col) = l;
                split2(c[mt][nt][2] * gx, c[mt][nt][3] * gy, h, l);
                *(uint32_t*)(Oh + (row0 + 8) * EE + col) = h;
                *(uint32_t*)(Ol + (row0 + 8) * EE + col) = l;
            }
        }
    } else if (mode == 2) {
#pragma unroll
        for (int mt = 0; mt < 4; mt++) {
            int row0 = rowBase + wm * 64 + mt * 16 + g;
            int s = row0 - batch * SS;
#pragma unroll
            for (int nt = 0; nt < 8; nt++) {
                int col = colBase + wn * 64 + nt * 8 + 2 * tig;
                int hh = col >> 6, d = col & 63;
                size_t vb = ((size_t)(batch * HH + hh) * 64 + d) * SS + s;
                g_Vt[vb]          = __float2half_rn(c[mt][nt][0] * INV32);
                g_Vt[vb + SS]     = __float2half_rn(c[mt][nt][1] * INV32);
                g_Vt[vb + 8]      = __float2half_rn(c[mt][nt][2] * INV32);
                g_Vt[vb + SS + 8] = __float2half_rn(c[mt][nt][3] * INV32);
            }
        }
    } else {
#pragma unroll
        for (int mt = 0; mt < 4; mt++) {
            size_t row0 = (size_t)rowBase + wm * 64 + mt * 16 + g;
#pragma unroll
            for (int nt = 0; nt < 8; nt++) {
                int col = colBase + wn * 64 + nt * 8 + 2 * tig;
                float2 x0 = *(const float2*)(AuxX + row0 * EE + col);
                float2 x1 = *(const float2*)(AuxX + (row0 + 8) * EE + col);
                *(float2*)(g_R + row0 * EE + col) =
                    make_float2(c[mt][nt][0] * INV32 + x0.x, c[mt][nt][1] * INV32 + x0.y);
                *(float2*)(g_R + (row0 + 8) * EE + col) =
                    make_float2(c[mt][nt][2] * INV32 + x1.x, c[mt][nt][3] * INV32 + x1.y);
            }
        }
    }
}

// ---------------- flash attention: fp16, PV single-term, 3 CTAs/SM ----------
#define AROW 144
#define ATILE (64 * AROW)                  /* 9216 */
#define ABUF (3 * ATILE)                   /* Kh, Kl, V = 27648 */
#define ATTN_SMEM (2 * ABUF)               /* 55296 */

__global__ __launch_bounds__(128, 3) void attn_kernel()
{
    extern __shared__ char smb[];
    const uint32_t sbase = smem_u32(smb);

    const int qt = blockIdx.x;     // 0..15 (64 q rows each)
    const int h  = blockIdx.y;
    const int b  = blockIdx.z;
    const int tid = threadIdx.x;
    const int wid = tid >> 5;      // 0..3
    const int lane = tid & 31;
    const int g = lane >> 2;
    const int tig = lane & 3;

    const size_t kbase0 = ((size_t)b * SS) * EE + h * 64;
    const size_t vbase0 = ((size_t)(b * HH + h) * 64) * SS;

    auto issue = [&](int kt, int stage) {
        uint32_t sb = sbase + stage * ABUF;
#pragma unroll
        for (int i = 0; i < 4; i++) {
            int ch = tid + i * 128;        // 0..511
            int r = ch >> 3;               // 0..63
            int cb = (ch & 7) * 16;
            int c8 = (ch & 7) * 8;
            size_t ko = kbase0 + (size_t)(kt * 64 + r) * EE + c8;
            size_t vo = vbase0 + (size_t)r * SS + kt * 64 + c8;
            uint32_t off = r * AROW + cb;
            cp16(sb + off,             g_Kh + ko);
            cp16(sb + ATILE + off,     g_Kl + ko);
            cp16(sb + 2 * ATILE + off, g_Vt + vo);
        }
        CP_COMMIT;
    };

    issue(0, 0);

    // ---- Q fragments (held all kernel; log2e pre-folded) ----
    uint32_t qh[4][4], ql[4][4];
    {
        size_t rg = (size_t)(b * SS + qt * 64 + wid * 16 + g);
        const __half* ph = g_Qh + rg * EE + h * 64;
        const __half* pl = g_Ql + rg * EE + h * 64;
#pragma unroll
        for (int ks = 0; ks < 4; ks++) {
            int c0 = ks * 16 + 2 * tig;
            qh[ks][0] = *(const uint32_t*)(ph + c0);
            qh[ks][1] = *(const uint32_t*)(ph + 8 * EE + c0);
            qh[ks][2] = *(const uint32_t*)(ph + c0 + 8);
            qh[ks][3] = *(const uint32_t*)(ph + 8 * EE + c0 + 8);
            ql[ks][0] = *(const uint32_t*)(pl + c0);
            ql[ks][1] = *(const uint32_t*)(pl + 8 * EE + c0);
            ql[ks][2] = *(const uint32_t*)(pl + c0 + 8);
            ql[ks][3] = *(const uint32_t*)(pl + 8 * EE + c0 + 8);
        }
    }

    float acc[8][4];
#pragma unroll
    for (int j = 0; j < 8; j++)
#pragma unroll
        for (int r = 0; r < 4; r++) acc[j][r] = 0.f;
    float m0 = -1e30f, m1 = -1e30f, l0 = 0.f, l1 = 0.f;

    const uint32_t fLane = (uint32_t)((lane & 7) + ((lane >> 4) & 1) * 8) * AROW
                         + ((lane >> 3) & 1) * 16;

    for (int kt = 0; kt < 16; kt++) {
        CP_WAIT(0);
        __syncthreads();
        if (kt < 15) issue(kt + 1, (kt + 1) & 1);

        const uint32_t sb = sbase + (kt & 1) * ABUF;
        const uint32_t kOff = sb + fLane;
        const uint32_t vOff = sb + 2 * ATILE + fLane;

        // ---- scores (log2 domain), fp16 3-term ----
        float c[8][4];
#pragma unroll
        for (int j = 0; j < 8; j++)
#pragma unroll
            for (int r = 0; r < 4; r++) c[j][r] = 0.f;

#pragma unroll
        for (int ks = 0; ks < 4; ks++) {
            uint32_t bh[4][4], bl[4][4];
#pragma unroll
            for (int p = 0; p < 4; p++) {
                ldsm4(bh[p], kOff + p * 16 * AROW + ks * 32);
                ldsm4(bl[p], kOff + ATILE + p * 16 * AROW + ks * 32);
            }
#pragma unroll
            for (int p = 0; p < 4; p++) {
                mma_f16(c[2 * p],     qh[ks], bh[p][0], bh[p][1]);
                mma_f16(c[2 * p + 1], qh[ks], bh[p][2], bh[p][3]);
            }
#pragma unroll
            for (int p = 0; p < 4; p++) {
                mma_f16(c[2 * p],     qh[ks], bl[p][0], bl[p][1]);
                mma_f16(c[2 * p + 1], qh[ks], bl[p][2], bl[p][3]);
            }
#pragma unroll
            for (int p = 0; p < 4; p++) {
                mma_f16(c[2 * p],     ql[ks], bh[p][0], bh[p][1]);
                mma_f16(c[2 * p + 1], ql[ks], bh[p][2], bh[p][3]);
            }
        }

        // ---- online softmax (exp2 domain) ----
        float mx0 = -1e30f, mx1 = -1e30f;
#pragma unroll
        for (int j = 0; j < 8; j++) {
            mx0 = fmaxf(mx0, fmaxf(c[j][0], c[j][1]));
            mx1 = fmaxf(mx1, fmaxf(c[j][2], c[j][3]));
        }
        mx0 = fmaxf(mx0, __shfl_xor_sync(0xffffffffu, mx0, 1));
        mx0 = fmaxf(mx0, __shfl_xor_sync(0xffffffffu, mx0, 2));
        mx1 = fmaxf(mx1, __shfl_xor_sync(0xffffffffu, mx1, 1));
        mx1 = fmaxf(mx1, __shfl_xor_sync(0xffffffffu, mx1, 2));
        float mn0 = fmaxf(m0, mx0), mn1 = fmaxf(m1, mx1);
        float cr0 = exp2f(m0 - mn0), cr1 = exp2f(m1 - mn1);
        float s0 = 0.f, s1 = 0.f;
#pragma unroll
        for (int j = 0; j < 8; j++) {
            c[j][0] = exp2f(c[j][0] - mn0);
            c[j][1] = exp2f(c[j][1] - mn0);
            c[j][2] = exp2f(c[j][2] - mn1);
            c[j][3] = exp2f(c[j][3] - mn1);
            s0 += c[j][0] + c[j][1];
            s1 += c[j][2] + c[j][3];
        }
        s0 += __shfl_xor_sync(0xffffffffu, s0, 1);
        s0 += __shfl_xor_sync(0xffffffffu, s0, 2);
        s1 += __shfl_xor_sync(0xffffffffu, s1, 1);
        s1 += __shfl_xor_sync(0xffffffffu, s1, 2);
        l0 = l0 * cr0 + s0;
        l1 = l1 * cr1 + s1;
        m0 = mn0; m1 = mn1;
#pragma unroll
        for (int j = 0; j < 8; j++) {
            acc[j][0] *= cr0; acc[j][1] *= cr0;
            acc[j][2] *= cr1; acc[j][3] *= cr1;
        }

        // ---- PV: single term, P and V fp16 ----
#pragma unroll
        for (int ks = 0; ks < 4; ks++) {
            uint32_t ph[4];
            ph[0] = packh2(c[2 * ks][0],     c[2 * ks][1]);
            ph[1] = packh2(c[2 * ks][2],     c[2 * ks][3]);
            ph[2] = packh2(c[2 * ks + 1][0], c[2 * ks + 1][1]);
            ph[3] = packh2(c[2 * ks + 1][2], c[2 * ks + 1][3]);
            uint32_t vh[4][4];
#pragma unroll
            for (int p = 0; p < 4; p++)
                ldsm4(vh[p], vOff + p * 16 * AROW + ks * 32);
#pragma unroll
            for (int p = 0; p < 4; p++) {
                mma_f16(acc[2 * p],     ph, vh[p][0], vh[p][1]);
                mma_f16(acc[2 * p + 1], ph, vh[p][2], vh[p][3]);
            }
        }
    }

    // ---- epilogue: O = acc/l, write fp16 hi/lo ----
    float i0 = 1.f / l0, i1 = 1.f / l1;
    size_t rg = (size_t)(b * SS + qt * 64 + wid * 16 + g);
#pragma unroll
    for (int j = 0; j < 8; j++) {
        int col = h * 64 + j * 8 + 2 * tig;
        uint32_t hh, ll;
        split2(acc[j][0] * i0, acc[j][1] * i0, hh, ll);
        *(uint32_t*)(g_Oh + rg * EE + col) = hh;
        *(uint32_t*)(g_Ol + rg * EE + col) = ll;
        split2(acc[j][2] * i1, acc[j][3] * i1, hh, ll);
        *(uint32_t*)(g_Oh + (rg + 8) * EE + col) = hh;
        *(uint32_t*)(g_Ol + (rg + 8) * EE + col) = ll;
    }
}

// ---------------- LayerNorm ----------------
__global__ __launch_bounds__(256) void ln_kernel(
    const float* __restrict__ gamma, const float* __restrict__ beta,
    float* __restrict__ out)
{
    const int row = blockIdx.x;
    const int tid = threadIdx.x;
    const float4 v = *(const float4*)(g_R + (size_t)row * EE + tid * 4);

    float s1 = v.x + v.y + v.z + v.w;
    float s2 = v.x * v.x + v.y * v.y + v.z * v.z + v.w * v.w;

    __shared__ float sh1[8], sh2[8];
#pragma unroll
    for (int off = 16; off > 0; off >>= 1) {
        s1 += __shfl_xor_sync(0xffffffffu, s1, off);
        s2 += __shfl_xor_sync(0xffffffffu, s2, off);
    }
    const int warp = tid >> 5;
    if ((tid & 31) == 0) { sh1[warp] = s1; sh2[warp] = s2; }
    __syncthreads();
    float t1 = 0.f, t2 = 0.f;
#pragma unroll
    for (int w = 0; w < 8; w++) { t1 += sh1[w]; t2 += sh2[w]; }

    const float mean = t1 * (1.0f / EE);
    const float var  = t2 * (1.0f / EE) - mean * mean;
    const float inv  = rsqrtf(var + 1e-6f);

    const float4 gmv = *(const float4*)(gamma + tid * 4);
    const float4 btv = *(const float4*)(beta + tid * 4);
    float4 o;
    o.x = (v.x - mean) * inv * gmv.x + btv.x;
    o.y = (v.y - mean) * inv * gmv.y + btv.y;
    o.z = (v.z - mean) * inv * gmv.z + btv.z;
    o.w = (v.w - mean) * inv * gmv.w + btv.w;
    *(float4*)(out + (size_t)row * EE + tid * 4) = o;
}

// ---------------------------------------------------------------------------
extern "C" void kernel_launch(void* const* d_in, const int* in_sizes, int n_in,
                              void* d_out, int out_size)
{
    const float* X     = (const float*)d_in[0];
    const float* gQ    = (const float*)d_in[1];
    const float* gK    = (const float*)d_in[2];
    const float* Wq    = (const float*)d_in[3];
    const float* Wk    = (const float*)d_in[4];
    const float* Wv    = (const float*)d_in[5];
    const float* Wo    = (const float*)d_in[6];
    const float* gamma = (const float*)d_in[7];
    const float* beta  = (const float*)d_in[8];
    float* out = (float*)d_out;

    cudaFuncSetAttribute(gemm_kernel,
                         cudaFuncAttributeMaxDynamicSharedMemorySize, GEMM_SMEM);
    cudaFuncSetAttribute(attn_kernel,
                         cudaFuncAttributeMaxDynamicSharedMemorySize, ATTN_SMEM);

    prep_x_kernel<<<NELEM / 1024, 256>>>(X);
    prep_w_kernel<<<dim3(32, 32, 4), dim3(32, 8)>>>(Wq, Wk, Wv, Wo);

    gemm_kernel<<<dim3(8, 64, 3), 128, GEMM_SMEM>>>(gQ, gK, X, 0);

    attn_kernel<<<dim3(16, HH, BB), 128, ATTN_SMEM>>>();

    gemm_kernel<<<dim3(8, 64, 1), 128, GEMM_SMEM>>>(gQ, gK, X, 3);
    ln_kernel<<<M_TOT, 256>>>(gamma, beta, out);
}